// round 11
// baseline (speedup 1.0000x reference)
#include <cuda_runtime.h>
#include <cuda_fp16.h>
#include <math.h>
#include <stdint.h>

#define S_LEN 2048
#define HID   4096
#define KVD   1024
#define NH    32
#define NKV   8
#define HD    128

__device__ float g_Q[S_LEN * HID];
__device__ float g_K[S_LEN * KVD];
__device__ float g_V[S_LEN * KVD];
__device__ float g_AO[S_LEN * HID];
__device__ __half g_Ah[S_LEN * HID];
__device__ __half g_Al[S_LEN * HID];      // lo, PRE-SCALED x256 (GEMM corr only)
__device__ __half g_Wh[HID * HID];
__device__ __half g_Wh2[KVD * HID];
__device__ __half g_Wh3[KVD * HID];
__device__ __half g_Qh[S_LEN * HID];
__device__ __half g_Ql[S_LEN * HID];
__device__ __half g_Kh[S_LEN * KVD];
__device__ __half g_Kl[S_LEN * KVD];
__device__ __half g_Vh[S_LEN * KVD];
__device__ __half g_Vl[S_LEN * KVD];
__device__ float g_cos[S_LEN * 64];
__device__ float g_sin[S_LEN * 64];
__device__ unsigned int g_work_ctr;

__device__ __forceinline__ uint32_t smem_u32(const void* p) {
    uint32_t a;
    asm("{ .reg .u64 t; cvta.to.shared.u64 t, %1; cvt.u32.u64 %0, t; }"
        : "=r"(a) : "l"(p));
    return a;
}
__device__ __forceinline__ void ldsm4(uint32_t* r, uint32_t addr) {
    asm volatile("ldmatrix.sync.aligned.m8n8.x4.shared.b16 {%0,%1,%2,%3}, [%4];"
                 : "=r"(r[0]), "=r"(r[1]), "=r"(r[2]), "=r"(r[3]) : "r"(addr));
}
__device__ __forceinline__ void ldsm4t(uint32_t* r, uint32_t addr) {
    asm volatile("ldmatrix.sync.aligned.m8n8.x4.trans.shared.b16 {%0,%1,%2,%3}, [%4];"
                 : "=r"(r[0]), "=r"(r[1]), "=r"(r[2]), "=r"(r[3]) : "r"(addr));
}
__device__ __forceinline__ void mma16816(float* d, const uint32_t* a,
                                         const uint32_t* b) {
    asm volatile(
        "mma.sync.aligned.m16n8k16.row.col.f32.f16.f16.f32 "
        "{%0,%1,%2,%3},{%4,%5,%6,%7},{%8,%9},{%0,%1,%2,%3};"
        : "+f"(d[0]), "+f"(d[1]), "+f"(d[2]), "+f"(d[3])
        : "r"(a[0]), "r"(a[1]), "r"(a[2]), "r"(a[3]), "r"(b[0]), "r"(b[1]));
}
__device__ __forceinline__ void mma16816_h(uint32_t* d, const uint32_t* a,
                                           const uint32_t* b) {
    asm volatile(
        "mma.sync.aligned.m16n8k16.row.col.f16.f16.f16.f16 "
        "{%0,%1},{%2,%3,%4,%5},{%6,%7},{%0,%1};"
        : "+r"(d[0]), "+r"(d[1])
        : "r"(a[0]), "r"(a[1]), "r"(a[2]), "r"(a[3]), "r"(b[0]), "r"(b[1]));
}
__device__ __forceinline__ void cp_async16(uint32_t dst, const void* src) {
    asm volatile("cp.async.cg.shared.global [%0], [%1], 16;"
                 :: "r"(dst), "l"(src) : "memory");
}
__device__ __forceinline__ uint32_t pack_f16(float x, float y) {
    __half2 h = __floats2half2_rn(x, y);
    return *(uint32_t*)&h;
}

// ---------------------------------------------------------------------------
// fp32 -> (fp16 hi, fp16 lo*lo_scale) split.
// ---------------------------------------------------------------------------
__global__ void split_f16_kernel(const float* __restrict__ src,
                                 __half* __restrict__ hi,
                                 __half* __restrict__ lo, int n, float lo_scale)
{
    int i = (blockIdx.x * blockDim.x + threadIdx.x) * 4;
    if (i >= n) return;
    float4 v = *(const float4*)(src + i);
    __half h0 = __float2half_rn(v.x);
    __half h1 = __float2half_rn(v.y);
    __half h2 = __float2half_rn(v.z);
    __half h3 = __float2half_rn(v.w);
    __half2* hp = (__half2*)(hi + i);
    __half2* lp = (__half2*)(lo + i);
    hp[0] = __half2(h0, h1); hp[1] = __half2(h2, h3);
    lp[0] = __floats2half2_rn((v.x - __half2float(h0)) * lo_scale,
                              (v.y - __half2float(h1)) * lo_scale);
    lp[1] = __floats2half2_rn((v.z - __half2float(h2)) * lo_scale,
                              (v.w - __half2float(h3)) * lo_scale);
}

__global__ void conv_f16_kernel(const float* __restrict__ src,
                                __half* __restrict__ dst, int n)
{
    int i = (blockIdx.x * blockDim.x + threadIdx.x) * 4;
    if (i >= n) return;
    float4 v = *(const float4*)(src + i);
    __half2* dp = (__half2*)(dst + i);
    dp[0] = __floats2half2_rn(v.x, v.y);
    dp[1] = __floats2half2_rn(v.z, v.w);
}

// ---------------------------------------------------------------------------
// GEMM tiles: CTA 256x128, 512 threads (16 warps, warp 64x32), BK=32, 3-stage.
// ---------------------------------------------------------------------------
#define BK 32
#define ASTR 40
#define GT_A (256 * ASTR * 2)        // 20480
#define GT_B (128 * ASTR * 2)        // 10240
#define GSTAGE (GT_A + GT_B)         // 30720
#define GNST 3
#define GSMEM (GNST * GSTAGE)        // 92160
#define KTILES (HID / BK)

// ---- main term: C = Ah * Bh^T  (fp32 accumulate) ----
__global__ __launch_bounds__(512, 1) void gemm_main_kernel(
    const __half* __restrict__ A,
    const __half* __restrict__ Bh0, float* __restrict__ C0,
    const __half* __restrict__ Bh1, float* __restrict__ C1, int N)
{
    extern __shared__ char smem[];
    const uint32_t sb = smem_u32(smem);
    const int tid  = threadIdx.x;
    const int wid  = tid >> 5;
    const int lane = tid & 31;
    const int wm   = wid & 3;
    const int wn   = wid >> 2;
    const int m0   = blockIdx.y * 256;
    const int n0   = blockIdx.x * 128;

    const __half* Bh = blockIdx.z ? Bh1 : Bh0;
    float* C = blockIdx.z ? C1 : C0;
    const __half* aSrc = A  + (size_t)m0 * HID;
    const __half* bSrc = Bh + (size_t)n0 * HID;

    auto load_stage = [&](int kt, int stage) {
        const int kc = kt * BK;
        const uint32_t sbase = sb + stage * GSTAGE;
#pragma unroll
        for (int i = 0; i < 2; i++) {
            int idx = tid + i * 512;
            int row = idx >> 2, kch = idx & 3;
            cp_async16(sbase + (uint32_t)(row * 80 + kch * 16),
                       aSrc + (size_t)row * HID + kc + kch * 8);
        }
        {
            int row = tid >> 2, kch = tid & 3;
            cp_async16(sbase + GT_A + (uint32_t)(row * 80 + kch * 16),
                       bSrc + (size_t)row * HID + kc + kch * 8);
        }
        asm volatile("cp.async.commit_group;" ::: "memory");
    };

    float acc[4][4][4];
#pragma unroll
    for (int i = 0; i < 4; i++)
#pragma unroll
        for (int j = 0; j < 4; j++)
#pragma unroll
            for (int q = 0; q < 4; q++) acc[i][j][q] = 0.0f;

    load_stage(0, 0);
    load_stage(1, 1);

    const int a_la  = lane & 15;
    const int a_k8  = (lane >> 4) << 3;
    const int b_r   = ((lane >> 4) << 3) + (lane & 7);
    const int b_k8  = ((lane >> 3) & 1) << 3;

    for (int kt = 0; kt < KTILES; kt++) {
        if (kt + 1 < KTILES)
            asm volatile("cp.async.wait_group 1;" ::: "memory");
        else
            asm volatile("cp.async.wait_group 0;" ::: "memory");
        __syncthreads();
        if (kt + 2 < KTILES) load_stage(kt + 2, (kt + 2) % GNST);

        const uint32_t sbase = sb + (kt % GNST) * GSTAGE;
        const uint32_t sA = sbase;
        const uint32_t sB = sbase + GT_A;

#pragma unroll
        for (int k16 = 0; k16 < 2; k16++) {
            uint32_t af[4][4], bf[2][4];
#pragma unroll
            for (int i = 0; i < 4; i++) {
                int arow = wm * 64 + i * 16 + a_la;
                ldsm4(af[i], sA + (uint32_t)(arow * ASTR + k16 * 16 + a_k8) * 2);
            }
#pragma unroll
            for (int jp = 0; jp < 2; jp++) {
                int brow = wn * 32 + jp * 16 + b_r;
                ldsm4(bf[jp], sB + (uint32_t)(brow * ASTR + k16 * 16 + b_k8) * 2);
            }
#pragma unroll
            for (int i = 0; i < 4; i++)
#pragma unroll
                for (int jp = 0; jp < 2; jp++) {
                    mma16816(acc[i][2 * jp],     af[i], bf[jp]);
                    mma16816(acc[i][2 * jp + 1], af[i], bf[jp] + 2);
                }
        }
    }

#pragma unroll
    for (int i = 0; i < 4; i++) {
        int row = m0 + wm * 64 + i * 16 + (lane >> 2);
#pragma unroll
        for (int j = 0; j < 4; j++) {
            int col = n0 + wn * 32 + j * 8 + (lane & 3) * 2;
            *(float2*)&C[(size_t)row * N + col] =
                make_float2(acc[i][j][0], acc[i][j][1]);
            *(float2*)&C[(size_t)(row + 8) * N + col] =
                make_float2(acc[i][j][2], acc[i][j][3]);
        }
    }
}

// ---- correction term: C += (Al*256) * Bh^T * 2^-8  (fp16 accumulate) ----
__global__ __launch_bounds__(512, 1) void gemm_corr_kernel(
    const __half* __restrict__ A,
    const __half* __restrict__ Bh0, float* __restrict__ C0,
    const __half* __restrict__ Bh1, float* __restrict__ C1, int N)
{
    extern __shared__ char smem[];
    const uint32_t sb = smem_u32(smem);
    const int tid  = threadIdx.x;
    const int wid  = tid >> 5;
    const int lane = tid & 31;
    const int wm   = wid & 3;
    const int wn   = wid >> 2;
    const int m0   = blockIdx.y * 256;
    const int n0   = blockIdx.x * 128;

    const __half* Bh = blockIdx.z ? Bh1 : Bh0;
    float* C = blockIdx.z ? C1 : C0;
    const __half* aSrc = A  + (size_t)m0 * HID;
    const __half* bSrc = Bh + (size_t)n0 * HID;

    auto load_stage = [&](int kt, int stage) {
        const int kc = kt * BK;
        const uint32_t sbase = sb + stage * GSTAGE;
#pragma unroll
        for (int i = 0; i < 2; i++) {
            int idx = tid + i * 512;
            int row = idx >> 2, kch = idx & 3;
            cp_async16(sbase + (uint32_t)(row * 80 + kch * 16),
                       aSrc + (size_t)row * HID + kc + kch * 8);
        }
        {
            int row = tid >> 2, kch = tid & 3;
            cp_async16(sbase + GT_A + (uint32_t)(row * 80 + kch * 16),
                       bSrc + (size_t)row * HID + kc + kch * 8);
        }
        asm volatile("cp.async.commit_group;" ::: "memory");
    };

    uint32_t acc[4][4][2];                   // fp16x2 accumulators
#pragma unroll
    for (int i = 0; i < 4; i++)
#pragma unroll
        for (int j = 0; j < 4; j++) { acc[i][j][0] = 0u; acc[i][j][1] = 0u; }

    load_stage(0, 0);
    load_stage(1, 1);

    const int a_la  = lane & 15;
    const int a_k8  = (lane >> 4) << 3;
    const int b_r   = ((lane >> 4) << 3) + (lane & 7);
    const int b_k8  = ((lane >> 3) & 1) << 3;

    for (int kt = 0; kt < KTILES; kt++) {
        if (kt + 1 < KTILES)
            asm volatile("cp.async.wait_group 1;" ::: "memory");
        else
            asm volatile("cp.async.wait_group 0;" ::: "memory");
        __syncthreads();
        if (kt + 2 < KTILES) load_stage(kt + 2, (kt + 2) % GNST);

        const uint32_t sbase = sb + (kt % GNST) * GSTAGE;
        const uint32_t sA = sbase;
        const uint32_t sB = sbase + GT_A;

#pragma unroll
        for (int k16 = 0; k16 < 2; k16++) {
            uint32_t af[4][4], bf[2][4];
#pragma unroll
            for (int i = 0; i < 4; i++) {
                int arow = wm * 64 + i * 16 + a_la;
                ldsm4(af[i], sA + (uint32_t)(arow * ASTR + k16 * 16 + a_k8) * 2);
            }
#pragma unroll
            for (int jp = 0; jp < 2; jp++) {
                int brow = wn * 32 + jp * 16 + b_r;
                ldsm4(bf[jp], sB + (uint32_t)(brow * ASTR + k16 * 16 + b_k8) * 2);
            }
#pragma unroll
            for (int i = 0; i < 4; i++)
#pragma unroll
                for (int jp = 0; jp < 2; jp++) {
                    mma16816_h(acc[i][2 * jp],     af[i], bf[jp]);
                    mma16816_h(acc[i][2 * jp + 1], af[i], bf[jp] + 2);
                }
        }
    }

    const float cs = 0.00390625f;            // 2^-8
#pragma unroll
    for (int i = 0; i < 4; i++) {
        int row = m0 + wm * 64 + i * 16 + (lane >> 2);
#pragma unroll
        for (int j = 0; j < 4; j++) {
            int col = n0 + wn * 32 + j * 8 + (lane & 3) * 2;
            float2 lo = __half22float2(*(__half2*)&acc[i][j][0]);
            float2 hi = __half22float2(*(__half2*)&acc[i][j][1]);
            float2 c0 = *(float2*)&C[(size_t)row * N + col];
            float2 c1 = *(float2*)&C[(size_t)(row + 8) * N + col];
            c0.x += lo.x * cs; c0.y += lo.y * cs;
            c1.x += hi.x * cs; c1.y += hi.y * cs;
            *(float2*)&C[(size_t)row * N + col] = c0;
            *(float2*)&C[(size_t)(row + 8) * N + col] = c1;
        }
    }
}

__global__ void rope_table_kernel(const int* __restrict__ pos)
{
    int idx = blockIdx.x * blockDim.x + threadIdx.x;
    int s = idx >> 6, i = idx & 63;
    double inv = exp(-((double)(2 * i) / 128.0) * 9.210340371976184);
    double ang = (double)pos[s] * inv;
    g_cos[idx] = (float)cos(ang);
    g_sin[idx] = (float)sin(ang);
}

__global__ void rope_split_kernel()
{
    const int s = blockIdx.x;
    const float qscale = 0.08838834764831845f;
    for (int idx = threadIdx.x; idx < (NH + NKV) * 64; idx += blockDim.x) {
        const float* src; __half *dh, *dl;
        int stride, head, i; float scale;
        if (idx < NH * 64) {
            src = g_Q; dh = g_Qh; dl = g_Ql; stride = HID;
            head = idx >> 6; i = idx & 63; scale = qscale;
        } else {
            int t = idx - NH * 64;
            src = g_K; dh = g_Kh; dl = g_Kl; stride = KVD;
            head = t >> 6; i = t & 63; scale = 1.0f;
        }
        float c  = g_cos[s * 64 + i];
        float sn = g_sin[s * 64 + i];
        size_t base = (size_t)s * stride + head * HD;
        float x0 = src[base + i];
        float x1 = src[base + i + 64];
        float y0 = (x0 * c - x1 * sn) * scale;
        float y1 = (x1 * c + x0 * sn) * scale;
        __half h0 = __float2half_rn(y0);
        __half h1 = __float2half_rn(y1);
        dh[base + i]      = h0;
        dh[base + i + 64] = h1;
        dl[base + i]      = __float2half_rn(y0 - __half2float(h0));
        dl[base + i + 64] = __float2half_rn(y1 - __half2float(h1));
    }
}

__global__ void zero_ctr_kernel() { g_work_ctr = 0u; }

// ---------------------------------------------------------------------------
// Persistent flash attention, fp16 3-term QK/PV, f32 softmax (unchanged).
// ---------------------------------------------------------------------------
#define QSTR 136
#define FTILE (64 * QSTR * 2)
#define FSTAGE (4 * FTILE)
#define FQOFF  (2 * FSTAGE)
#define FQSZ   (128 * QSTR * 2)
#define FSMEM  (FQOFF + 2 * FQSZ)
#define FSMEM_TOT (FSMEM + 16)
#define NITEMS (NH * 16)

__global__ __launch_bounds__(256, 1) void flash_mma_kernel(
    const __half* __restrict__ Qh, const __half* __restrict__ Ql,
    const __half* __restrict__ Kh, const __half* __restrict__ Kl,
    const __half* __restrict__ Vh, const __half* __restrict__ Vl,
    float* __restrict__ O)
{
    extern __shared__ char smem[];
    const uint32_t sb = smem_u32(smem);
    int* sWork = (int*)(smem + FSMEM);
    const int tid = threadIdx.x;
    const int lane = tid & 31;
    const int w = tid >> 5;

    const int a_la = lane & 15;
    const int a_k8 = (lane >> 4) << 3;
    const int b_r  = ((lane >> 4) << 3) + (lane & 7);
    const int b_k8 = ((lane >> 3) & 1) << 3;
    const int r0 = lane >> 2;
    const uint32_t sQh = sb + FQOFF;
    const uint32_t sQl = sQh + FQSZ;

    while (true) {
        if (tid == 0) *sWork = (int)atomicAdd(&g_work_ctr, 1u);
        __syncthreads();
        const int j = *sWork;
        if (j >= NITEMS) break;
        const int h  = j & 31;
        const int qb = 15 - (j >> 5);
        const int kvh = h >> 2;
        const int ntiles = 2 * (qb + 1);
        const int qrow0 = qb * 128 + w * 16;

        const __half* qsrc[2] = {
            Qh + (size_t)(qb * 128) * HID + h * HD,
            Ql + (size_t)(qb * 128) * HID + h * HD };
        const __half* tsrc[4] = {
            Kh + (size_t)kvh * HD, Kl + (size_t)kvh * HD,
            Vh + (size_t)kvh * HD, Vl + (size_t)kvh * HD };

#pragma unroll
        for (int s2 = 0; s2 < 2; s2++)
#pragma unroll
            for (int i = 0; i < 8; i++) {
                int idx = tid + i * 256;
                int row = idx >> 4, ch = idx & 15;
                cp_async16(sb + FQOFF + s2 * FQSZ + (uint32_t)(row * 272 + ch * 16),
                           qsrc[s2] + (size_t)row * HID + ch * 8);
            }
        asm volatile("cp.async.commit_group;" ::: "memory");

        auto load_tile = [&](int t, int buf) {
#pragma unroll
            for (int sub = 0; sub < 4; sub++) {
                const __half* src = tsrc[sub];
                const uint32_t tb = sb + buf * FSTAGE + sub * FTILE;
#pragma unroll
                for (int i = 0; i < 4; i++) {
                    int idx = tid + i * 256;
                    int row = idx >> 4, ch = idx & 15;
                    cp_async16(tb + (uint32_t)(row * 272 + ch * 16),
                               src + (size_t)(t * 64 + row) * KVD + ch * 8);
                }
            }
            asm volatile("cp.async.commit_group;" ::: "memory");
        };

        load_tile(0, 0);
        if (ntiles > 1) load_tile(1, 1);

        float m[2] = {-1e30f, -1e30f}, l[2] = {0.0f, 0.0f};
        float o[16][4];
#pragma unroll
        for (int jj = 0; jj < 16; jj++)
#pragma unroll
            for (int q = 0; q < 4; q++) o[jj][q] = 0.0f;

        for (int t = 0; t < ntiles; t++) {
            if (t + 1 < ntiles)
                asm volatile("cp.async.wait_group 1;" ::: "memory");
            else
                asm volatile("cp.async.wait_group 0;" ::: "memory");
            __syncthreads();

            const uint32_t stg = sb + (t & 1) * FSTAGE;
            const uint32_t sKh = stg, sKl = stg + FTILE;
            const uint32_t sVh = stg + 2 * FTILE, sVl = stg + 3 * FTILE;

            const bool skip = (qrow0 + 15) < t * 64;
            if (!skip) {
                float sc[8][4];
#pragma unroll
                for (int nt = 0; nt < 8; nt++)
#pragma unroll
                    for (int q = 0; q < 4; q++) sc[nt][q] = 0.0f;

#pragma unroll
                for (int ks = 0; ks < 8; ks++) {
                    uint32_t aoff = (uint32_t)((w * 16 + a_la) * QSTR + ks * 16 + a_k8) * 2;
                    uint32_t aqh[4], aql[4];
                    ldsm4(aqh, sQh + aoff);
                    ldsm4(aql, sQl + aoff);
                    uint32_t bh[4][4], bl[4][4];
#pragma unroll
                    for (int np = 0; np < 4; np++) {
                        uint32_t boff = (uint32_t)((np * 16 + b_r) * QSTR + ks * 16 + b_k8) * 2;
                        ldsm4(bh[np], sKh + boff);
                        ldsm4(bl[np], sKl + boff);
                    }
#pragma unroll
                    for (int np = 0; np < 4; np++) {
                        mma16816(sc[2 * np],     aqh, bh[np]);
                        mma16816(sc[2 * np + 1], aqh, bh[np] + 2);
                    }
#pragma unroll
                    for (int np = 0; np < 4; np++) {
                        mma16816(sc[2 * np],     aqh, bl[np]);
                        mma16816(sc[2 * np + 1], aqh, bl[np] + 2);
                    }
#pragma unroll
                    for (int np = 0; np < 4; np++) {
                        mma16816(sc[2 * np],     aql, bh[np]);
                        mma16816(sc[2 * np + 1], aql, bh[np] + 2);
                    }
                }

                if (t * 64 + 63 > qrow0) {
#pragma unroll
                    for (int nt = 0; nt < 8; nt++)
#pragma unroll
                        for (int e = 0; e < 4; e++) {
                            int col = t * 64 + nt * 8 + (lane & 3) * 2 + (e & 1);
                            int row = qrow0 + r0 + ((e >> 1) << 3);
                            if (col > row) sc[nt][e] = -1e30f;
                        }
                }

#pragma unroll
                for (int rr = 0; rr < 2; rr++) {
                    float mt = -1e30f;
#pragma unroll
                    for (int nt = 0; nt < 8; nt++)
                        mt = fmaxf(mt, fmaxf(sc[nt][rr * 2], sc[nt][rr * 2 + 1]));
                    mt = fmaxf(mt, __shfl_xor_sync(0xffffffffu, mt, 1));
                    mt = fmaxf(mt, __shfl_xor_sync(0xffffffffu, mt, 2));
                    float mn = fmaxf(m[rr], mt);
                    float alpha = __expf(m[rr] - mn);
                    m[rr] = mn;
                    float sum = 0.0f;
#pragma unroll
                    for (int nt = 0; nt < 8; nt++) {
                        float p0 = __expf(sc[nt][rr * 2]     - mn);
                        float p1 = __expf(sc[nt][rr * 2 + 1] - mn);
                        sc[nt][rr * 2] = p0; sc[nt][rr * 2 + 1] = p1;
                        sum += p0 + p1;
                    }
                    sum += __shfl_xor_sync(0xffffffffu, sum, 1);
                    sum += __shfl_xor_sync(0xffffffffu, sum, 2);
                    l[rr] = l[rr] * alpha + sum;
#pragma unroll
                    for (int jj = 0; jj < 16; jj++) {
                        o[jj][rr * 2]     *= alpha;
                        o[jj][rr * 2 + 1] *= alpha;
                    }
                }

                uint32_t ph[4][4], pl[4][4];
#pragma unroll
                for (int ks2 = 0; ks2 < 4; ks2++)
#pragma unroll
                    for (int half = 0; half < 2; half++) {
                        int nt = 2 * ks2 + half;
#pragma unroll
                        for (int rr = 0; rr < 2; rr++) {
                            float p0 = sc[nt][rr * 2], p1 = sc[nt][rr * 2 + 1];
                            __half h0 = __float2half_rn(p0);
                            __half h1 = __float2half_rn(p1);
                            __half2 hp = __half2(h0, h1);
                            ph[ks2][half * 2 + rr] = *(uint32_t*)&hp;
                            pl[ks2][half * 2 + rr] =
                                pack_f16(p0 - __half2float(h0),
                                         p1 - __half2float(h1));
                        }
                    }

#pragma unroll
                for (int ks2 = 0; ks2 < 4; ks2++) {
#pragma unroll
                    for (int g = 0; g < 2; g++) {
                        uint32_t vh[4][4], vl[4][4];
#pragma unroll
                        for (int q = 0; q < 4; q++) {
                            int np = g * 4 + q;
                            uint32_t voff = (uint32_t)((ks2 * 16 + a_la) * QSTR + np * 16 + a_k8) * 2;
                            ldsm4t(vh[q], sVh + voff);
                            ldsm4t(vl[q], sVl + voff);
                        }
#pragma unroll
                        for (int q = 0; q < 4; q++) {
                            int np = g * 4 + q;
                            mma16816(o[2 * np],     ph[ks2], vh[q]);
                            mma16816(o[2 * np + 1], ph[ks2], vh[q] + 2);
                        }
#pragma unroll
                        for (int q = 0; q < 4; q++) {
                            int np = g * 4 + q;
                            mma16816(o[2 * np],     ph[ks2], vl[q]);
                            mma16816(o[2 * np + 1], ph[ks2], vl[q] + 2);
                        }
#pragma unroll
                        for (int q = 0; q < 4; q++) {
                            int np = g * 4 + q;
                            mma16816(o[2 * np],     pl[ks2], vh[q]);
                            mma16816(o[2 * np + 1], pl[ks2], vh[q] + 2);
                        }
                    }
                }
            }
            __syncthreads();
            if (t + 2 < ntiles) load_tile(t + 2, t & 1);
        }

#pragma unroll
        for (int rr = 0; rr < 2; rr++) {
            float inv = 1.0f / l[rr];
            int grow = qrow0 + r0 + rr * 8;
#pragma unroll
            for (int jj = 0; jj < 16; jj++) {
                int col = h * HD + jj * 8 + (lane & 3) * 2;
                *(float2*)&O[(size_t)grow * HID + col] =
                    make_float2(o[jj][rr * 2] * inv, o[jj][rr * 2 + 1] * inv);
            }
        }
    }
}

extern "C" void kernel_launch(void* const* d_in, const int* in_sizes, int n_in,
                              void* d_out, int out_size)
{
    const float* hidden = (const float*)d_in[0];
    const int*   pos    = (const int*)d_in[1];
    const float* Wq     = (const float*)d_in[2];
    const float* Wk     = (const float*)d_in[3];
    const float* Wv     = (const float*)d_in[4];
    const float* Wo     = (const float*)d_in[5];
    float* out = (float*)d_out;

    float *qp, *kp, *vp, *aop;
    __half *ah, *al, *wh, *wh2, *wh3;
    __half *qhp, *qlp, *khp, *klp, *vhp, *vlp;
    cudaGetSymbolAddress((void**)&qp,  g_Q);
    cudaGetSymbolAddress((void**)&kp,  g_K);
    cudaGetSymbolAddress((void**)&vp,  g_V);
    cudaGetSymbolAddress((void**)&aop, g_AO);
    cudaGetSymbolAddress((void**)&ah,  g_Ah);
    cudaGetSymbolAddress((void**)&al,  g_Al);
    cudaGetSymbolAddress((void**)&wh,  g_Wh);
    cudaGetSymbolAddress((void**)&wh2, g_Wh2);
    cudaGetSymbolAddress((void**)&wh3, g_Wh3);
    cudaGetSymbolAddress((void**)&qhp, g_Qh);
    cudaGetSymbolAddress((void**)&qlp, g_Ql);
    cudaGetSymbolAddress((void**)&khp, g_Kh);
    cudaGetSymbolAddress((void**)&klp, g_Kl);
    cudaGetSymbolAddress((void**)&vhp, g_Vh);
    cudaGetSymbolAddress((void**)&vlp, g_Vl);

    cudaFuncSetAttribute(gemm_main_kernel,
                         cudaFuncAttributeMaxDynamicSharedMemorySize, GSMEM);
    cudaFuncSetAttribute(gemm_corr_kernel,
                         cudaFuncAttributeMaxDynamicSharedMemorySize, GSMEM);
    cudaFuncSetAttribute(flash_mma_kernel,
                         cudaFuncAttributeMaxDynamicSharedMemorySize, FSMEM_TOT);

    const int NA  = S_LEN * HID;
    const int NWQ = HID * HID;
    const int NWK = KVD * HID;

    // (1) act split (lo x256), (2) Wq conv, (3) main Q, (4) corr Q <- ncu
    split_f16_kernel<<<NA / 4 / 256, 256>>>(hidden, ah, al, NA, 256.0f);
    conv_f16_kernel<<<NWQ / 4 / 256, 256>>>(Wq, wh, NWQ);
    gemm_main_kernel<<<dim3(HID / 128, S_LEN / 256, 1), 512, GSMEM>>>(
        ah, wh, qp, wh, qp, HID);
    gemm_corr_kernel<<<dim3(HID / 128, S_LEN / 256, 1), 512, GSMEM>>>(
        al, wh, qp, wh, qp, HID);

    conv_f16_kernel<<<NWK / 4 / 256, 256>>>(Wk, wh2, NWK);
    conv_f16_kernel<<<NWK / 4 / 256, 256>>>(Wv, wh3, NWK);
    gemm_main_kernel<<<dim3(KVD / 128, S_LEN / 256, 2), 512, GSMEM>>>(
        ah, wh2, kp, wh3, vp, KVD);
    gemm_corr_kernel<<<dim3(KVD / 128, S_LEN / 256, 2), 512, GSMEM>>>(
        al, wh2, kp, wh3, vp, KVD);

    rope_table_kernel<<<S_LEN * 64 / 256, 256>>>(pos);
    rope_split_kernel<<<S_LEN, 256>>>();
    split_f16_kernel<<<S_LEN * KVD / 4 / 256, 256>>>(vp, vhp, vlp,
                                                     S_LEN * KVD, 1.0f);

    zero_ctr_kernel<<<1, 1>>>();
    flash_mma_kernel<<<148, 256, FSMEM_TOT>>>(
        qhp, qlp, khp, klp, vhp, vlp, aop);

    split_f16_kernel<<<NA / 4 / 256, 256>>>(aop, ah, al, NA, 256.0f);
    conv_f16_kernel<<<NWQ / 4 / 256, 256>>>(Wo, wh, NWQ);
    gemm_main_kernel<<<dim3(HID / 128, S_LEN / 256, 1), 512, GSMEM>>>(
        ah, wh, out, wh, out, HID);
    gemm_corr_kernel<<<dim3(HID / 128, S_LEN / 256, 1), 512, GSMEM>>>(
        al, wh, out, wh, out, HID);
}

// round 12
// speedup vs baseline: 1.2742x; 1.2742x over previous
#include <cuda_runtime.h>
#include <cuda_fp16.h>
#include <math.h>
#include <stdint.h>

#define S_LEN 2048
#define HID   4096
#define KVD   1024
#define NH    32
#define NKV   8
#define HD    128

__device__ float g_Q[S_LEN * HID];
__device__ float g_K[S_LEN * KVD];
__device__ float g_V[S_LEN * KVD];
__device__ float g_AO[S_LEN * HID];
__device__ __half g_Ah[S_LEN * HID];
__device__ __half g_Al[S_LEN * HID];
__device__ __half g_Wh[HID * HID];
__device__ __half g_Wh2[KVD * HID];
__device__ __half g_Wh3[KVD * HID];
__device__ __half g_Qh[S_LEN * HID];
__device__ __half g_Kh[S_LEN * KVD];
__device__ __half g_Kl[S_LEN * KVD];
__device__ __half g_Vh[S_LEN * KVD];
__device__ __half g_Vl[S_LEN * KVD];
__device__ float g_cos[S_LEN * 64];
__device__ float g_sin[S_LEN * 64];
__device__ unsigned int g_work_ctr;

__device__ __forceinline__ uint32_t smem_u32(const void* p) {
    uint32_t a;
    asm("{ .reg .u64 t; cvta.to.shared.u64 t, %1; cvt.u32.u64 %0, t; }"
        : "=r"(a) : "l"(p));
    return a;
}
__device__ __forceinline__ void ldsm4(uint32_t* r, uint32_t addr) {
    asm volatile("ldmatrix.sync.aligned.m8n8.x4.shared.b16 {%0,%1,%2,%3}, [%4];"
                 : "=r"(r[0]), "=r"(r[1]), "=r"(r[2]), "=r"(r[3]) : "r"(addr));
}
__device__ __forceinline__ void ldsm4t(uint32_t* r, uint32_t addr) {
    asm volatile("ldmatrix.sync.aligned.m8n8.x4.trans.shared.b16 {%0,%1,%2,%3}, [%4];"
                 : "=r"(r[0]), "=r"(r[1]), "=r"(r[2]), "=r"(r[3]) : "r"(addr));
}
__device__ __forceinline__ void mma16816(float* d, const uint32_t* a,
                                         const uint32_t* b) {
    asm volatile(
        "mma.sync.aligned.m16n8k16.row.col.f32.f16.f16.f32 "
        "{%0,%1,%2,%3},{%4,%5,%6,%7},{%8,%9},{%0,%1,%2,%3};"
        : "+f"(d[0]), "+f"(d[1]), "+f"(d[2]), "+f"(d[3])
        : "r"(a[0]), "r"(a[1]), "r"(a[2]), "r"(a[3]), "r"(b[0]), "r"(b[1]));
}
__device__ __forceinline__ void cp_async16(uint32_t dst, const void* src) {
    asm volatile("cp.async.cg.shared.global [%0], [%1], 16;"
                 :: "r"(dst), "l"(src) : "memory");
}

// ---------------------------------------------------------------------------
// fp32 -> (fp16 hi, fp16 lo) split / plain convert
// ---------------------------------------------------------------------------
__global__ void split_f16_kernel(const float* __restrict__ src,
                                 __half* __restrict__ hi,
                                 __half* __restrict__ lo, int n)
{
    int i = (blockIdx.x * blockDim.x + threadIdx.x) * 4;
    if (i >= n) return;
    float4 v = *(const float4*)(src + i);
    __half h0 = __float2half_rn(v.x);
    __half h1 = __float2half_rn(v.y);
    __half h2 = __float2half_rn(v.z);
    __half h3 = __float2half_rn(v.w);
    __half2* hp = (__half2*)(hi + i);
    __half2* lp = (__half2*)(lo + i);
    hp[0] = __half2(h0, h1); hp[1] = __half2(h2, h3);
    lp[0] = __floats2half2_rn(v.x - __half2float(h0), v.y - __half2float(h1));
    lp[1] = __floats2half2_rn(v.z - __half2float(h2), v.w - __half2float(h3));
}

__global__ void conv_f16_kernel(const float* __restrict__ src,
                                __half* __restrict__ dst, int n)
{
    int i = (blockIdx.x * blockDim.x + threadIdx.x) * 4;
    if (i >= n) return;
    float4 v = *(const float4*)(src + i);
    __half2* dp = (__half2*)(dst + i);
    dp[0] = __floats2half2_rn(v.x, v.y);
    dp[1] = __floats2half2_rn(v.z, v.w);
}

// ---------------------------------------------------------------------------
// GEMM common: CTA 256x128, 512 threads (16 warps, warp 64x32), BK=32, 3-stage.
// ---------------------------------------------------------------------------
#define BK 32
#define ASTR 40
#define GT_A (256 * ASTR * 2)        // 20480
#define GT_B (128 * ASTR * 2)        // 10240
#define KTILES (HID / BK)

// ---- 2-term: C = (Ah+Al) * Bh^T  (Q and O projections) ----
#define G2STAGE (2 * GT_A + GT_B)    // 51200
#define G2SMEM (3 * G2STAGE)         // 153600

__global__ __launch_bounds__(512, 1) void gemm2_kernel(
    const __half* __restrict__ Ah, const __half* __restrict__ Al,
    const __half* __restrict__ Bh, float* __restrict__ C, int N)
{
    extern __shared__ char smem[];
    const uint32_t sb = smem_u32(smem);
    const int tid  = threadIdx.x;
    const int wid  = tid >> 5;
    const int lane = tid & 31;
    const int wm   = wid & 3;
    const int wn   = wid >> 2;
    const int m0   = blockIdx.y * 256;
    const int n0   = blockIdx.x * 128;

    const __half* aS[2] = { Ah + (size_t)m0 * HID, Al + (size_t)m0 * HID };
    const __half* bSrc  = Bh + (size_t)n0 * HID;

    auto load_stage = [&](int kt, int stage) {
        const int kc = kt * BK;
        const uint32_t sbase = sb + stage * G2STAGE;
#pragma unroll
        for (int t = 0; t < 2; t++) {
            const uint32_t tb = sbase + t * GT_A;
#pragma unroll
            for (int i = 0; i < 2; i++) {
                int idx = tid + i * 512;
                int row = idx >> 2, kch = idx & 3;
                cp_async16(tb + (uint32_t)(row * 80 + kch * 16),
                           aS[t] + (size_t)row * HID + kc + kch * 8);
            }
        }
        {
            const uint32_t tb = sbase + 2 * GT_A;
            int row = tid >> 2, kch = tid & 3;
            cp_async16(tb + (uint32_t)(row * 80 + kch * 16),
                       bSrc + (size_t)row * HID + kc + kch * 8);
        }
        asm volatile("cp.async.commit_group;" ::: "memory");
    };

    float acc[4][4][4];
#pragma unroll
    for (int i = 0; i < 4; i++)
#pragma unroll
        for (int j = 0; j < 4; j++)
#pragma unroll
            for (int q = 0; q < 4; q++) acc[i][j][q] = 0.0f;

    load_stage(0, 0);
    load_stage(1, 1);

    const int a_la  = lane & 15;
    const int a_k8  = (lane >> 4) << 3;
    const int b_r   = ((lane >> 4) << 3) + (lane & 7);
    const int b_k8  = ((lane >> 3) & 1) << 3;

    for (int kt = 0; kt < KTILES; kt++) {
        if (kt + 1 < KTILES)
            asm volatile("cp.async.wait_group 1;" ::: "memory");
        else
            asm volatile("cp.async.wait_group 0;" ::: "memory");
        __syncthreads();
        if (kt + 2 < KTILES) load_stage(kt + 2, (kt + 2) % 3);

        const uint32_t sbase = sb + (kt % 3) * G2STAGE;
        const uint32_t sAh = sbase;
        const uint32_t sAl = sbase + GT_A;
        const uint32_t sBh = sbase + 2 * GT_A;

#pragma unroll
        for (int k16 = 0; k16 < 2; k16++) {
            uint32_t ah[4][4], al[4][4], bf[2][4];
#pragma unroll
            for (int i = 0; i < 4; i++) {
                int arow = wm * 64 + i * 16 + a_la;
                uint32_t off = (uint32_t)(arow * ASTR + k16 * 16 + a_k8) * 2;
                ldsm4(ah[i], sAh + off);
                ldsm4(al[i], sAl + off);
            }
#pragma unroll
            for (int jp = 0; jp < 2; jp++) {
                int brow = wn * 32 + jp * 16 + b_r;
                ldsm4(bf[jp], sBh + (uint32_t)(brow * ASTR + k16 * 16 + b_k8) * 2);
            }
#pragma unroll
            for (int i = 0; i < 4; i++)
#pragma unroll
                for (int jp = 0; jp < 2; jp++) {
                    mma16816(acc[i][2 * jp],     ah[i], bf[jp]);
                    mma16816(acc[i][2 * jp + 1], ah[i], bf[jp] + 2);
                }
#pragma unroll
            for (int i = 0; i < 4; i++)
#pragma unroll
                for (int jp = 0; jp < 2; jp++) {
                    mma16816(acc[i][2 * jp],     al[i], bf[jp]);
                    mma16816(acc[i][2 * jp + 1], al[i], bf[jp] + 2);
                }
        }
    }

#pragma unroll
    for (int i = 0; i < 4; i++) {
        int row = m0 + wm * 64 + i * 16 + (lane >> 2);
#pragma unroll
        for (int j = 0; j < 4; j++) {
            int col = n0 + wn * 32 + j * 8 + (lane & 3) * 2;
            *(float2*)&C[(size_t)row * N + col] =
                make_float2(acc[i][j][0], acc[i][j][1]);
            *(float2*)&C[(size_t)(row + 8) * N + col] =
                make_float2(acc[i][j][2], acc[i][j][3]);
        }
    }
}

// ---- 1-term: C = Ah * Bh^T  (K and V projections, z selects set) ----
#define G1STAGE (GT_A + GT_B)        // 30720
#define G1SMEM (3 * G1STAGE)         // 92160

__global__ __launch_bounds__(512, 1) void gemm1_kernel(
    const __half* __restrict__ A,
    const __half* __restrict__ Bh0, float* __restrict__ C0,
    const __half* __restrict__ Bh1, float* __restrict__ C1, int N)
{
    extern __shared__ char smem[];
    const uint32_t sb = smem_u32(smem);
    const int tid  = threadIdx.x;
    const int wid  = tid >> 5;
    const int lane = tid & 31;
    const int wm   = wid & 3;
    const int wn   = wid >> 2;
    const int m0   = blockIdx.y * 256;
    const int n0   = blockIdx.x * 128;

    const __half* Bh = blockIdx.z ? Bh1 : Bh0;
    float* C = blockIdx.z ? C1 : C0;
    const __half* aSrc = A  + (size_t)m0 * HID;
    const __half* bSrc = Bh + (size_t)n0 * HID;

    auto load_stage = [&](int kt, int stage) {
        const int kc = kt * BK;
        const uint32_t sbase = sb + stage * G1STAGE;
#pragma unroll
        for (int i = 0; i < 2; i++) {
            int idx = tid + i * 512;
            int row = idx >> 2, kch = idx & 3;
            cp_async16(sbase + (uint32_t)(row * 80 + kch * 16),
                       aSrc + (size_t)row * HID + kc + kch * 8);
        }
        {
            int row = tid >> 2, kch = tid & 3;
            cp_async16(sbase + GT_A + (uint32_t)(row * 80 + kch * 16),
                       bSrc + (size_t)row * HID + kc + kch * 8);
        }
        asm volatile("cp.async.commit_group;" ::: "memory");
    };

    float acc[4][4][4];
#pragma unroll
    for (int i = 0; i < 4; i++)
#pragma unroll
        for (int j = 0; j < 4; j++)
#pragma unroll
            for (int q = 0; q < 4; q++) acc[i][j][q] = 0.0f;

    load_stage(0, 0);
    load_stage(1, 1);

    const int a_la  = lane & 15;
    const int a_k8  = (lane >> 4) << 3;
    const int b_r   = ((lane >> 4) << 3) + (lane & 7);
    const int b_k8  = ((lane >> 3) & 1) << 3;

    for (int kt = 0; kt < KTILES; kt++) {
        if (kt + 1 < KTILES)
            asm volatile("cp.async.wait_group 1;" ::: "memory");
        else
            asm volatile("cp.async.wait_group 0;" ::: "memory");
        __syncthreads();
        if (kt + 2 < KTILES) load_stage(kt + 2, (kt + 2) % 3);

        const uint32_t sbase = sb + (kt % 3) * G1STAGE;
        const uint32_t sA = sbase;
        const uint32_t sB = sbase + GT_A;

#pragma unroll
        for (int k16 = 0; k16 < 2; k16++) {
            uint32_t af[4][4], bf[2][4];
#pragma unroll
            for (int i = 0; i < 4; i++) {
                int arow = wm * 64 + i * 16 + a_la;
                ldsm4(af[i], sA + (uint32_t)(arow * ASTR + k16 * 16 + a_k8) * 2);
            }
#pragma unroll
            for (int jp = 0; jp < 2; jp++) {
                int brow = wn * 32 + jp * 16 + b_r;
                ldsm4(bf[jp], sB + (uint32_t)(brow * ASTR + k16 * 16 + b_k8) * 2);
            }
#pragma unroll
            for (int i = 0; i < 4; i++)
#pragma unroll
                for (int jp = 0; jp < 2; jp++) {
                    mma16816(acc[i][2 * jp],     af[i], bf[jp]);
                    mma16816(acc[i][2 * jp + 1], af[i], bf[jp] + 2);
                }
        }
    }

#pragma unroll
    for (int i = 0; i < 4; i++) {
        int row = m0 + wm * 64 + i * 16 + (lane >> 2);
#pragma unroll
        for (int j = 0; j < 4; j++) {
            int col = n0 + wn * 32 + j * 8 + (lane & 3) * 2;
            *(float2*)&C[(size_t)row * N + col] =
                make_float2(acc[i][j][0], acc[i][j][1]);
            *(float2*)&C[(size_t)(row + 8) * N + col] =
                make_float2(acc[i][j][2], acc[i][j][3]);
        }
    }
}

__global__ void rope_table_kernel(const int* __restrict__ pos)
{
    int idx = blockIdx.x * blockDim.x + threadIdx.x;
    int s = idx >> 6, i = idx & 63;
    double inv = exp(-((double)(2 * i) / 128.0) * 9.210340371976184);
    double ang = (double)pos[s] * inv;
    g_cos[idx] = (float)cos(ang);
    g_sin[idx] = (float)sin(ang);
}

// RoPE + scale(Q) + convert: Q -> hi only; K -> hi + lo.
__global__ void rope_split_kernel()
{
    const int s = blockIdx.x;
    const float qscale = 0.08838834764831845f;
    for (int idx = threadIdx.x; idx < (NH + NKV) * 64; idx += blockDim.x) {
        float c, sn;
        if (idx < NH * 64) {
            int head = idx >> 6, i = idx & 63;
            c = g_cos[s * 64 + i]; sn = g_sin[s * 64 + i];
            size_t base = (size_t)s * HID + head * HD;
            float x0 = g_Q[base + i];
            float x1 = g_Q[base + i + 64];
            g_Qh[base + i]      = __float2half_rn((x0 * c - x1 * sn) * qscale);
            g_Qh[base + i + 64] = __float2half_rn((x1 * c + x0 * sn) * qscale);
        } else {
            int t = idx - NH * 64;
            int head = t >> 6, i = t & 63;
            c = g_cos[s * 64 + i]; sn = g_sin[s * 64 + i];
            size_t base = (size_t)s * KVD + head * HD;
            float x0 = g_K[base + i];
            float x1 = g_K[base + i + 64];
            float y0 = x0 * c - x1 * sn;
            float y1 = x1 * c + x0 * sn;
            __half h0 = __float2half_rn(y0);
            __half h1 = __float2half_rn(y1);
            g_Kh[base + i]      = h0;
            g_Kh[base + i + 64] = h1;
            g_Kl[base + i]      = __float2half_rn(y0 - __half2float(h0));
            g_Kl[base + i + 64] = __float2half_rn(y1 - __half2float(h1));
        }
    }
}

__global__ void zero_ctr_kernel() { g_work_ctr = 0u; }

// ---------------------------------------------------------------------------
// Persistent flash attention.
// QK: Qh*Kh + Qh*Kl (2-term).  PV: Ph*Vh + Ph*Vl (2-term).
// ---------------------------------------------------------------------------
#define QSTR 136
#define FTILE (64 * QSTR * 2)
#define FSTAGE (4 * FTILE)           // Kh, Kl, Vh, Vl
#define FQOFF  (2 * FSTAGE)          // 139264
#define FQSZ   (128 * QSTR * 2)      // 34816
#define FSMEM  (FQOFF + FQSZ)        // 174080
#define FSMEM_TOT (FSMEM + 16)
#define NITEMS (NH * 16)

__global__ __launch_bounds__(256, 1) void flash_mma_kernel(
    const __half* __restrict__ Qh,
    const __half* __restrict__ Kh, const __half* __restrict__ Kl,
    const __half* __restrict__ Vh, const __half* __restrict__ Vl,
    float* __restrict__ O)
{
    extern __shared__ char smem[];
    const uint32_t sb = smem_u32(smem);
    int* sWork = (int*)(smem + FSMEM);
    const int tid = threadIdx.x;
    const int lane = tid & 31;
    const int w = tid >> 5;

    const int a_la = lane & 15;
    const int a_k8 = (lane >> 4) << 3;
    const int b_r  = ((lane >> 4) << 3) + (lane & 7);
    const int b_k8 = ((lane >> 3) & 1) << 3;
    const int r0 = lane >> 2;
    const uint32_t sQh = sb + FQOFF;

    while (true) {
        if (tid == 0) *sWork = (int)atomicAdd(&g_work_ctr, 1u);
        __syncthreads();
        const int j = *sWork;
        if (j >= NITEMS) break;
        const int h  = j & 31;
        const int qb = 15 - (j >> 5);
        const int kvh = h >> 2;
        const int ntiles = 2 * (qb + 1);
        const int qrow0 = qb * 128 + w * 16;

        const __half* qsrc = Qh + (size_t)(qb * 128) * HID + h * HD;
        const __half* tsrc[4] = {
            Kh + (size_t)kvh * HD, Kl + (size_t)kvh * HD,
            Vh + (size_t)kvh * HD, Vl + (size_t)kvh * HD };

#pragma unroll
        for (int i = 0; i < 8; i++) {
            int idx = tid + i * 256;
            int row = idx >> 4, ch = idx & 15;
            cp_async16(sb + FQOFF + (uint32_t)(row * 272 + ch * 16),
                       qsrc + (size_t)row * HID + ch * 8);
        }
        asm volatile("cp.async.commit_group;" ::: "memory");

        auto load_tile = [&](int t, int buf) {
#pragma unroll
            for (int sub = 0; sub < 4; sub++) {
                const __half* src = tsrc[sub];
                const uint32_t tb = sb + buf * FSTAGE + sub * FTILE;
#pragma unroll
                for (int i = 0; i < 4; i++) {
                    int idx = tid + i * 256;
                    int row = idx >> 4, ch = idx & 15;
                    cp_async16(tb + (uint32_t)(row * 272 + ch * 16),
                               src + (size_t)(t * 64 + row) * KVD + ch * 8);
                }
            }
            asm volatile("cp.async.commit_group;" ::: "memory");
        };

        load_tile(0, 0);
        if (ntiles > 1) load_tile(1, 1);

        float m[2] = {-1e30f, -1e30f}, l[2] = {0.0f, 0.0f};
        float o[16][4];
#pragma unroll
        for (int jj = 0; jj < 16; jj++)
#pragma unroll
            for (int q = 0; q < 4; q++) o[jj][q] = 0.0f;

        for (int t = 0; t < ntiles; t++) {
            if (t + 1 < ntiles)
                asm volatile("cp.async.wait_group 1;" ::: "memory");
            else
                asm volatile("cp.async.wait_group 0;" ::: "memory");
            __syncthreads();

            const uint32_t stg = sb + (t & 1) * FSTAGE;
            const uint32_t sKh = stg, sKl = stg + FTILE;
            const uint32_t sVh = stg + 2 * FTILE, sVl = stg + 3 * FTILE;

            const bool skip = (qrow0 + 15) < t * 64;
            if (!skip) {
                // ---- S = Q K^T: Qh*Kh + Qh*Kl ----
                float sc[8][4];
#pragma unroll
                for (int nt = 0; nt < 8; nt++)
#pragma unroll
                    for (int q = 0; q < 4; q++) sc[nt][q] = 0.0f;

#pragma unroll
                for (int ks = 0; ks < 8; ks++) {
                    uint32_t aoff = (uint32_t)((w * 16 + a_la) * QSTR + ks * 16 + a_k8) * 2;
                    uint32_t aqh[4];
                    ldsm4(aqh, sQh + aoff);
                    uint32_t bh[4][4], bl[4][4];
#pragma unroll
                    for (int np = 0; np < 4; np++) {
                        uint32_t boff = (uint32_t)((np * 16 + b_r) * QSTR + ks * 16 + b_k8) * 2;
                        ldsm4(bh[np], sKh + boff);
                        ldsm4(bl[np], sKl + boff);
                    }
#pragma unroll
                    for (int np = 0; np < 4; np++) {
                        mma16816(sc[2 * np],     aqh, bh[np]);
                        mma16816(sc[2 * np + 1], aqh, bh[np] + 2);
                    }
#pragma unroll
                    for (int np = 0; np < 4; np++) {
                        mma16816(sc[2 * np],     aqh, bl[np]);
                        mma16816(sc[2 * np + 1], aqh, bl[np] + 2);
                    }
                }

                // ---- causal mask ----
                if (t * 64 + 63 > qrow0) {
#pragma unroll
                    for (int nt = 0; nt < 8; nt++)
#pragma unroll
                        for (int e = 0; e < 4; e++) {
                            int col = t * 64 + nt * 8 + (lane & 3) * 2 + (e & 1);
                            int row = qrow0 + r0 + ((e >> 1) << 3);
                            if (col > row) sc[nt][e] = -1e30f;
                        }
                }

                // ---- online softmax ----
#pragma unroll
                for (int rr = 0; rr < 2; rr++) {
                    float mt = -1e30f;
#pragma unroll
                    for (int nt = 0; nt < 8; nt++)
                        mt = fmaxf(mt, fmaxf(sc[nt][rr * 2], sc[nt][rr * 2 + 1]));
                    mt = fmaxf(mt, __shfl_xor_sync(0xffffffffu, mt, 1));
                    mt = fmaxf(mt, __shfl_xor_sync(0xffffffffu, mt, 2));
                    float mn = fmaxf(m[rr], mt);
                    float alpha = __expf(m[rr] - mn);
                    m[rr] = mn;
                    float sum = 0.0f;
#pragma unroll
                    for (int nt = 0; nt < 8; nt++) {
                        float p0 = __expf(sc[nt][rr * 2]     - mn);
                        float p1 = __expf(sc[nt][rr * 2 + 1] - mn);
                        sc[nt][rr * 2] = p0; sc[nt][rr * 2 + 1] = p1;
                        sum += p0 + p1;
                    }
                    sum += __shfl_xor_sync(0xffffffffu, sum, 1);
                    sum += __shfl_xor_sync(0xffffffffu, sum, 2);
                    l[rr] = l[rr] * alpha + sum;
#pragma unroll
                    for (int jj = 0; jj < 16; jj++) {
                        o[jj][rr * 2]     *= alpha;
                        o[jj][rr * 2 + 1] *= alpha;
                    }
                }

                // ---- pack P (hi only) into A fragments ----
                uint32_t ph[4][4];
#pragma unroll
                for (int ks2 = 0; ks2 < 4; ks2++)
#pragma unroll
                    for (int half = 0; half < 2; half++) {
                        int nt = 2 * ks2 + half;
#pragma unroll
                        for (int rr = 0; rr < 2; rr++) {
                            __half2 hp = __floats2half2_rn(sc[nt][rr * 2],
                                                           sc[nt][rr * 2 + 1]);
                            ph[ks2][half * 2 + rr] = *(uint32_t*)&hp;
                        }
                    }

                // ---- O += P V: Ph*Vh + Ph*Vl ----
#pragma unroll
                for (int ks2 = 0; ks2 < 4; ks2++) {
#pragma unroll
                    for (int g = 0; g < 2; g++) {
                        uint32_t vh[4][4], vl[4][4];
#pragma unroll
                        for (int q = 0; q < 4; q++) {
                            int np = g * 4 + q;
                            uint32_t voff = (uint32_t)((ks2 * 16 + a_la) * QSTR + np * 16 + a_k8) * 2;
                            ldsm4t(vh[q], sVh + voff);
                            ldsm4t(vl[q], sVl + voff);
                        }
#pragma unroll
                        for (int q = 0; q < 4; q++) {
                            int np = g * 4 + q;
                            mma16816(o[2 * np],     ph[ks2], vh[q]);
                            mma16816(o[2 * np + 1], ph[ks2], vh[q] + 2);
                        }
#pragma unroll
                        for (int q = 0; q < 4; q++) {
                            int np = g * 4 + q;
                            mma16816(o[2 * np],     ph[ks2], vl[q]);
                            mma16816(o[2 * np + 1], ph[ks2], vl[q] + 2);
                        }
                    }
                }
            }
            __syncthreads();
            if (t + 2 < ntiles) load_tile(t + 2, t & 1);
        }

#pragma unroll
        for (int rr = 0; rr < 2; rr++) {
            float inv = 1.0f / l[rr];
            int grow = qrow0 + r0 + rr * 8;
#pragma unroll
            for (int jj = 0; jj < 16; jj++) {
                int col = h * HD + jj * 8 + (lane & 3) * 2;
                *(float2*)&O[(size_t)grow * HID + col] =
                    make_float2(o[jj][rr * 2] * inv, o[jj][rr * 2 + 1] * inv);
            }
        }
    }
}

extern "C" void kernel_launch(void* const* d_in, const int* in_sizes, int n_in,
                              void* d_out, int out_size)
{
    const float* hidden = (const float*)d_in[0];
    const int*   pos    = (const int*)d_in[1];
    const float* Wq     = (const float*)d_in[2];
    const float* Wk     = (const float*)d_in[3];
    const float* Wv     = (const float*)d_in[4];
    const float* Wo     = (const float*)d_in[5];
    float* out = (float*)d_out;

    float *qp, *kp, *vp, *aop;
    __half *ah, *al, *wh, *wh2, *wh3;
    __half *qhp, *khp, *klp, *vhp, *vlp;
    cudaGetSymbolAddress((void**)&qp,  g_Q);
    cudaGetSymbolAddress((void**)&kp,  g_K);
    cudaGetSymbolAddress((void**)&vp,  g_V);
    cudaGetSymbolAddress((void**)&aop, g_AO);
    cudaGetSymbolAddress((void**)&ah,  g_Ah);
    cudaGetSymbolAddress((void**)&al,  g_Al);
    cudaGetSymbolAddress((void**)&wh,  g_Wh);
    cudaGetSymbolAddress((void**)&wh2, g_Wh2);
    cudaGetSymbolAddress((void**)&wh3, g_Wh3);
    cudaGetSymbolAddress((void**)&qhp, g_Qh);
    cudaGetSymbolAddress((void**)&khp, g_Kh);
    cudaGetSymbolAddress((void**)&klp, g_Kl);
    cudaGetSymbolAddress((void**)&vhp, g_Vh);
    cudaGetSymbolAddress((void**)&vlp, g_Vl);

    cudaFuncSetAttribute(gemm2_kernel,
                         cudaFuncAttributeMaxDynamicSharedMemorySize, G2SMEM);
    cudaFuncSetAttribute(gemm1_kernel,
                         cudaFuncAttributeMaxDynamicSharedMemorySize, G1SMEM);
    cudaFuncSetAttribute(flash_mma_kernel,
                         cudaFuncAttributeMaxDynamicSharedMemorySize, FSMEM_TOT);

    const int NA  = S_LEN * HID;
    const int NWQ = HID * HID;
    const int NWK = KVD * HID;

    // (1) act split, (2) Wq conv, (3) Wk conv, (4) gemm2 Q <- ncu capture
    split_f16_kernel<<<NA / 4 / 256, 256>>>(hidden, ah, al, NA);
    conv_f16_kernel<<<NWQ / 4 / 256, 256>>>(Wq, wh, NWQ);
    conv_f16_kernel<<<NWK / 4 / 256, 256>>>(Wk, wh2, NWK);
    gemm2_kernel<<<dim3(HID / 128, S_LEN / 256), 512, G2SMEM>>>(
        ah, al, wh, qp, HID);

    // K + V projections, 1-term, fused
    conv_f16_kernel<<<NWK / 4 / 256, 256>>>(Wv, wh3, NWK);
    gemm1_kernel<<<dim3(KVD / 128, S_LEN / 256, 2), 512, G1SMEM>>>(
        ah, wh2, kp, wh3, vp, KVD);

    rope_table_kernel<<<S_LEN * 64 / 256, 256>>>(pos);
    rope_split_kernel<<<S_LEN, 256>>>();
    split_f16_kernel<<<S_LEN * KVD / 4 / 256, 256>>>(vp, vhp, vlp, S_LEN * KVD);

    zero_ctr_kernel<<<1, 1>>>();
    flash_mma_kernel<<<148, 256, FSMEM_TOT>>>(
        qhp, khp, klp, vhp, vlp, aop);

    // O projection, 2-term
    split_f16_kernel<<<NA / 4 / 256, 256>>>(aop, ah, al, NA);
    conv_f16_kernel<<<NWQ / 4 / 256, 256>>>(Wo, wh, NWQ);
    gemm2_kernel<<<dim3(HID / 128, S_LEN / 256), 512, G2SMEM>>>(
        ah, al, wh, out, HID);
}

// round 13
// speedup vs baseline: 1.7418x; 1.3669x over previous
#include <cuda_runtime.h>
#include <cuda_fp16.h>
#include <math.h>
#include <stdint.h>

#define S_LEN 2048
#define HID   4096
#define KVD   1024
#define NH    32
#define NKV   8
#define HD    128

__device__ float g_Q[S_LEN * HID];
__device__ float g_K[S_LEN * KVD];
__device__ float g_V[S_LEN * KVD];
__device__ float g_AO[S_LEN * HID];
__device__ __half g_Ah[S_LEN * HID];
__device__ __half g_Wh[HID * HID];
__device__ __half g_Wh2[KVD * HID];
__device__ __half g_Wh3[KVD * HID];
__device__ __half g_Qh[S_LEN * HID];
__device__ __half g_Kh[S_LEN * KVD];
__device__ __half g_Kl[S_LEN * KVD];
__device__ __half g_Vh[S_LEN * KVD];
__device__ __half g_Vl[S_LEN * KVD];
__device__ float g_cos[S_LEN * 64];
__device__ float g_sin[S_LEN * 64];
__device__ unsigned int g_work_ctr;

__device__ __forceinline__ uint32_t smem_u32(const void* p) {
    uint32_t a;
    asm("{ .reg .u64 t; cvta.to.shared.u64 t, %1; cvt.u32.u64 %0, t; }"
        : "=r"(a) : "l"(p));
    return a;
}
__device__ __forceinline__ void ldsm4(uint32_t* r, uint32_t addr) {
    asm volatile("ldmatrix.sync.aligned.m8n8.x4.shared.b16 {%0,%1,%2,%3}, [%4];"
                 : "=r"(r[0]), "=r"(r[1]), "=r"(r[2]), "=r"(r[3]) : "r"(addr));
}
__device__ __forceinline__ void ldsm4t(uint32_t* r, uint32_t addr) {
    asm volatile("ldmatrix.sync.aligned.m8n8.x4.trans.shared.b16 {%0,%1,%2,%3}, [%4];"
                 : "=r"(r[0]), "=r"(r[1]), "=r"(r[2]), "=r"(r[3]) : "r"(addr));
}
__device__ __forceinline__ void mma16816(float* d, const uint32_t* a,
                                         const uint32_t* b) {
    asm volatile(
        "mma.sync.aligned.m16n8k16.row.col.f32.f16.f16.f32 "
        "{%0,%1,%2,%3},{%4,%5,%6,%7},{%8,%9},{%0,%1,%2,%3};"
        : "+f"(d[0]), "+f"(d[1]), "+f"(d[2]), "+f"(d[3])
        : "r"(a[0]), "r"(a[1]), "r"(a[2]), "r"(a[3]), "r"(b[0]), "r"(b[1]));
}
__device__ __forceinline__ void cp_async16(uint32_t dst, const void* src) {
    asm volatile("cp.async.cg.shared.global [%0], [%1], 16;"
                 :: "r"(dst), "l"(src) : "memory");
}

// ---------------------------------------------------------------------------
// fp32 -> fp16 convert / hi+lo split (split used for V only)
// ---------------------------------------------------------------------------
__global__ void conv_f16_kernel(const float* __restrict__ src,
                                __half* __restrict__ dst, int n)
{
    int i = (blockIdx.x * blockDim.x + threadIdx.x) * 4;
    if (i >= n) return;
    float4 v = *(const float4*)(src + i);
    __half2* dp = (__half2*)(dst + i);
    dp[0] = __floats2half2_rn(v.x, v.y);
    dp[1] = __floats2half2_rn(v.z, v.w);
}

__global__ void split_f16_kernel(const float* __restrict__ src,
                                 __half* __restrict__ hi,
                                 __half* __restrict__ lo, int n)
{
    int i = (blockIdx.x * blockDim.x + threadIdx.x) * 4;
    if (i >= n) return;
    float4 v = *(const float4*)(src + i);
    __half h0 = __float2half_rn(v.x);
    __half h1 = __float2half_rn(v.y);
    __half h2 = __float2half_rn(v.z);
    __half h3 = __float2half_rn(v.w);
    __half2* hp = (__half2*)(hi + i);
    __half2* lp = (__half2*)(lo + i);
    hp[0] = __half2(h0, h1); hp[1] = __half2(h2, h3);
    lp[0] = __floats2half2_rn(v.x - __half2float(h0), v.y - __half2float(h1));
    lp[1] = __floats2half2_rn(v.z - __half2float(h2), v.w - __half2float(h3));
}

// ---------------------------------------------------------------------------
// 1-term fp16 GEMM: C = A * B^T (fp32 acc).
// CTA 256x128, 512 threads (16 warps, warp 64x32), BK=32, 3-stage cp.async.
// blockIdx.z selects B/C set (fused launches).
// ---------------------------------------------------------------------------
#define BK 32
#define ASTR 40
#define GT_A (256 * ASTR * 2)        // 20480
#define GT_B (128 * ASTR * 2)        // 10240
#define G1STAGE (GT_A + GT_B)        // 30720
#define G1SMEM (3 * G1STAGE)         // 92160
#define KTILES (HID / BK)

__global__ __launch_bounds__(512, 1) void gemm1_kernel(
    const __half* __restrict__ A,
    const __half* __restrict__ Bh0, float* __restrict__ C0,
    const __half* __restrict__ Bh1, float* __restrict__ C1, int N)
{
    extern __shared__ char smem[];
    const uint32_t sb = smem_u32(smem);
    const int tid  = threadIdx.x;
    const int wid  = tid >> 5;
    const int lane = tid & 31;
    const int wm   = wid & 3;
    const int wn   = wid >> 2;
    const int m0   = blockIdx.y * 256;
    const int n0   = blockIdx.x * 128;

    const __half* Bh = blockIdx.z ? Bh1 : Bh0;
    float* C = blockIdx.z ? C1 : C0;
    const __half* aSrc = A  + (size_t)m0 * HID;
    const __half* bSrc = Bh + (size_t)n0 * HID;

    auto load_stage = [&](int kt, int stage) {
        const int kc = kt * BK;
        const uint32_t sbase = sb + stage * G1STAGE;
#pragma unroll
        for (int i = 0; i < 2; i++) {
            int idx = tid + i * 512;
            int row = idx >> 2, kch = idx & 3;
            cp_async16(sbase + (uint32_t)(row * 80 + kch * 16),
                       aSrc + (size_t)row * HID + kc + kch * 8);
        }
        {
            int row = tid >> 2, kch = tid & 3;
            cp_async16(sbase + GT_A + (uint32_t)(row * 80 + kch * 16),
                       bSrc + (size_t)row * HID + kc + kch * 8);
        }
        asm volatile("cp.async.commit_group;" ::: "memory");
    };

    float acc[4][4][4];
#pragma unroll
    for (int i = 0; i < 4; i++)
#pragma unroll
        for (int j = 0; j < 4; j++)
#pragma unroll
            for (int q = 0; q < 4; q++) acc[i][j][q] = 0.0f;

    load_stage(0, 0);
    load_stage(1, 1);

    const int a_la  = lane & 15;
    const int a_k8  = (lane >> 4) << 3;
    const int b_r   = ((lane >> 4) << 3) + (lane & 7);
    const int b_k8  = ((lane >> 3) & 1) << 3;

    for (int kt = 0; kt < KTILES; kt++) {
        if (kt + 1 < KTILES)
            asm volatile("cp.async.wait_group 1;" ::: "memory");
        else
            asm volatile("cp.async.wait_group 0;" ::: "memory");
        __syncthreads();
        if (kt + 2 < KTILES) load_stage(kt + 2, (kt + 2) % 3);

        const uint32_t sbase = sb + (kt % 3) * G1STAGE;
        const uint32_t sA = sbase;
        const uint32_t sB = sbase + GT_A;

#pragma unroll
        for (int k16 = 0; k16 < 2; k16++) {
            uint32_t af[4][4], bf[2][4];
#pragma unroll
            for (int i = 0; i < 4; i++) {
                int arow = wm * 64 + i * 16 + a_la;
                ldsm4(af[i], sA + (uint32_t)(arow * ASTR + k16 * 16 + a_k8) * 2);
            }
#pragma unroll
            for (int jp = 0; jp < 2; jp++) {
                int brow = wn * 32 + jp * 16 + b_r;
                ldsm4(bf[jp], sB + (uint32_t)(brow * ASTR + k16 * 16 + b_k8) * 2);
            }
#pragma unroll
            for (int i = 0; i < 4; i++)
#pragma unroll
                for (int jp = 0; jp < 2; jp++) {
                    mma16816(acc[i][2 * jp],     af[i], bf[jp]);
                    mma16816(acc[i][2 * jp + 1], af[i], bf[jp] + 2);
                }
        }
    }

#pragma unroll
    for (int i = 0; i < 4; i++) {
        int row = m0 + wm * 64 + i * 16 + (lane >> 2);
#pragma unroll
        for (int j = 0; j < 4; j++) {
            int col = n0 + wn * 32 + j * 8 + (lane & 3) * 2;
            *(float2*)&C[(size_t)row * N + col] =
                make_float2(acc[i][j][0], acc[i][j][1]);
            *(float2*)&C[(size_t)(row + 8) * N + col] =
                make_float2(acc[i][j][2], acc[i][j][3]);
        }
    }
}

__global__ void rope_table_kernel(const int* __restrict__ pos)
{
    int idx = blockIdx.x * blockDim.x + threadIdx.x;
    int s = idx >> 6, i = idx & 63;
    double inv = exp(-((double)(2 * i) / 128.0) * 9.210340371976184);
    double ang = (double)pos[s] * inv;
    g_cos[idx] = (float)cos(ang);
    g_sin[idx] = (float)sin(ang);
}

// RoPE + scale(Q) + convert: Q -> hi only; K -> hi + lo.
__global__ void rope_split_kernel()
{
    const int s = blockIdx.x;
    const float qscale = 0.08838834764831845f;
    for (int idx = threadIdx.x; idx < (NH + NKV) * 64; idx += blockDim.x) {
        float c, sn;
        if (idx < NH * 64) {
            int head = idx >> 6, i = idx & 63;
            c = g_cos[s * 64 + i]; sn = g_sin[s * 64 + i];
            size_t base = (size_t)s * HID + head * HD;
            float x0 = g_Q[base + i];
            float x1 = g_Q[base + i + 64];
            g_Qh[base + i]      = __float2half_rn((x0 * c - x1 * sn) * qscale);
            g_Qh[base + i + 64] = __float2half_rn((x1 * c + x0 * sn) * qscale);
        } else {
            int t = idx - NH * 64;
            int head = t >> 6, i = t & 63;
            c = g_cos[s * 64 + i]; sn = g_sin[s * 64 + i];
            size_t base = (size_t)s * KVD + head * HD;
            float x0 = g_K[base + i];
            float x1 = g_K[base + i + 64];
            float y0 = x0 * c - x1 * sn;
            float y1 = x1 * c + x0 * sn;
            __half h0 = __float2half_rn(y0);
            __half h1 = __float2half_rn(y1);
            g_Kh[base + i]      = h0;
            g_Kh[base + i + 64] = h1;
            g_Kl[base + i]      = __float2half_rn(y0 - __half2float(h0));
            g_Kl[base + i + 64] = __float2half_rn(y1 - __half2float(h1));
        }
    }
}

__global__ void zero_ctr_kernel() { g_work_ctr = 0u; }

// ---------------------------------------------------------------------------
// Persistent flash attention.
// QK: Qh*Kh + Qh*Kl (2-term).  PV: Ph*Vh + Ph*Vl (2-term).
// ---------------------------------------------------------------------------
#define QSTR 136
#define FTILE (64 * QSTR * 2)
#define FSTAGE (4 * FTILE)           // Kh, Kl, Vh, Vl
#define FQOFF  (2 * FSTAGE)          // 139264
#define FQSZ   (128 * QSTR * 2)      // 34816
#define FSMEM  (FQOFF + FQSZ)        // 174080
#define FSMEM_TOT (FSMEM + 16)
#define NITEMS (NH * 16)

__global__ __launch_bounds__(256, 1) void flash_mma_kernel(
    const __half* __restrict__ Qh,
    const __half* __restrict__ Kh, const __half* __restrict__ Kl,
    const __half* __restrict__ Vh, const __half* __restrict__ Vl,
    float* __restrict__ O)
{
    extern __shared__ char smem[];
    const uint32_t sb = smem_u32(smem);
    int* sWork = (int*)(smem + FSMEM);
    const int tid = threadIdx.x;
    const int lane = tid & 31;
    const int w = tid >> 5;

    const int a_la = lane & 15;
    const int a_k8 = (lane >> 4) << 3;
    const int b_r  = ((lane >> 4) << 3) + (lane & 7);
    const int b_k8 = ((lane >> 3) & 1) << 3;
    const int r0 = lane >> 2;
    const uint32_t sQh = sb + FQOFF;

    while (true) {
        if (tid == 0) *sWork = (int)atomicAdd(&g_work_ctr, 1u);
        __syncthreads();
        const int j = *sWork;
        if (j >= NITEMS) break;
        const int h  = j & 31;
        const int qb = 15 - (j >> 5);
        const int kvh = h >> 2;
        const int ntiles = 2 * (qb + 1);
        const int qrow0 = qb * 128 + w * 16;

        const __half* qsrc = Qh + (size_t)(qb * 128) * HID + h * HD;
        const __half* tsrc[4] = {
            Kh + (size_t)kvh * HD, Kl + (size_t)kvh * HD,
            Vh + (size_t)kvh * HD, Vl + (size_t)kvh * HD };

#pragma unroll
        for (int i = 0; i < 8; i++) {
            int idx = tid + i * 256;
            int row = idx >> 4, ch = idx & 15;
            cp_async16(sb + FQOFF + (uint32_t)(row * 272 + ch * 16),
                       qsrc + (size_t)row * HID + ch * 8);
        }
        asm volatile("cp.async.commit_group;" ::: "memory");

        auto load_tile = [&](int t, int buf) {
#pragma unroll
            for (int sub = 0; sub < 4; sub++) {
                const __half* src = tsrc[sub];
                const uint32_t tb = sb + buf * FSTAGE + sub * FTILE;
#pragma unroll
                for (int i = 0; i < 4; i++) {
                    int idx = tid + i * 256;
                    int row = idx >> 4, ch = idx & 15;
                    cp_async16(tb + (uint32_t)(row * 272 + ch * 16),
                               src + (size_t)(t * 64 + row) * KVD + ch * 8);
                }
            }
            asm volatile("cp.async.commit_group;" ::: "memory");
        };

        load_tile(0, 0);
        if (ntiles > 1) load_tile(1, 1);

        float m[2] = {-1e30f, -1e30f}, l[2] = {0.0f, 0.0f};
        float o[16][4];
#pragma unroll
        for (int jj = 0; jj < 16; jj++)
#pragma unroll
            for (int q = 0; q < 4; q++) o[jj][q] = 0.0f;

        for (int t = 0; t < ntiles; t++) {
            if (t + 1 < ntiles)
                asm volatile("cp.async.wait_group 1;" ::: "memory");
            else
                asm volatile("cp.async.wait_group 0;" ::: "memory");
            __syncthreads();

            const uint32_t stg = sb + (t & 1) * FSTAGE;
            const uint32_t sKh = stg, sKl = stg + FTILE;
            const uint32_t sVh = stg + 2 * FTILE, sVl = stg + 3 * FTILE;

            const bool skip = (qrow0 + 15) < t * 64;
            if (!skip) {
                float sc[8][4];
#pragma unroll
                for (int nt = 0; nt < 8; nt++)
#pragma unroll
                    for (int q = 0; q < 4; q++) sc[nt][q] = 0.0f;

#pragma unroll
                for (int ks = 0; ks < 8; ks++) {
                    uint32_t aoff = (uint32_t)((w * 16 + a_la) * QSTR + ks * 16 + a_k8) * 2;
                    uint32_t aqh[4];
                    ldsm4(aqh, sQh + aoff);
                    uint32_t bh[4][4], bl[4][4];
#pragma unroll
                    for (int np = 0; np < 4; np++) {
                        uint32_t boff = (uint32_t)((np * 16 + b_r) * QSTR + ks * 16 + b_k8) * 2;
                        ldsm4(bh[np], sKh + boff);
                        ldsm4(bl[np], sKl + boff);
                    }
#pragma unroll
                    for (int np = 0; np < 4; np++) {
                        mma16816(sc[2 * np],     aqh, bh[np]);
                        mma16816(sc[2 * np + 1], aqh, bh[np] + 2);
                    }
#pragma unroll
                    for (int np = 0; np < 4; np++) {
                        mma16816(sc[2 * np],     aqh, bl[np]);
                        mma16816(sc[2 * np + 1], aqh, bl[np] + 2);
                    }
                }

                if (t * 64 + 63 > qrow0) {
#pragma unroll
                    for (int nt = 0; nt < 8; nt++)
#pragma unroll
                        for (int e = 0; e < 4; e++) {
                            int col = t * 64 + nt * 8 + (lane & 3) * 2 + (e & 1);
                            int row = qrow0 + r0 + ((e >> 1) << 3);
                            if (col > row) sc[nt][e] = -1e30f;
                        }
                }

#pragma unroll
                for (int rr = 0; rr < 2; rr++) {
                    float mt = -1e30f;
#pragma unroll
                    for (int nt = 0; nt < 8; nt++)
                        mt = fmaxf(mt, fmaxf(sc[nt][rr * 2], sc[nt][rr * 2 + 1]));
                    mt = fmaxf(mt, __shfl_xor_sync(0xffffffffu, mt, 1));
                    mt = fmaxf(mt, __shfl_xor_sync(0xffffffffu, mt, 2));
                    float mn = fmaxf(m[rr], mt);
                    float alpha = __expf(m[rr] - mn);
                    m[rr] = mn;
                    float sum = 0.0f;
#pragma unroll
                    for (int nt = 0; nt < 8; nt++) {
                        float p0 = __expf(sc[nt][rr * 2]     - mn);
                        float p1 = __expf(sc[nt][rr * 2 + 1] - mn);
                        sc[nt][rr * 2] = p0; sc[nt][rr * 2 + 1] = p1;
                        sum += p0 + p1;
                    }
                    sum += __shfl_xor_sync(0xffffffffu, sum, 1);
                    sum += __shfl_xor_sync(0xffffffffu, sum, 2);
                    l[rr] = l[rr] * alpha + sum;
#pragma unroll
                    for (int jj = 0; jj < 16; jj++) {
                        o[jj][rr * 2]     *= alpha;
                        o[jj][rr * 2 + 1] *= alpha;
                    }
                }

                uint32_t ph[4][4];
#pragma unroll
                for (int ks2 = 0; ks2 < 4; ks2++)
#pragma unroll
                    for (int half = 0; half < 2; half++) {
                        int nt = 2 * ks2 + half;
#pragma unroll
                        for (int rr = 0; rr < 2; rr++) {
                            __half2 hp = __floats2half2_rn(sc[nt][rr * 2],
                                                           sc[nt][rr * 2 + 1]);
                            ph[ks2][half * 2 + rr] = *(uint32_t*)&hp;
                        }
                    }

#pragma unroll
                for (int ks2 = 0; ks2 < 4; ks2++) {
#pragma unroll
                    for (int g = 0; g < 2; g++) {
                        uint32_t vh[4][4], vl[4][4];
#pragma unroll
                        for (int q = 0; q < 4; q++) {
                            int np = g * 4 + q;
                            uint32_t voff = (uint32_t)((ks2 * 16 + a_la) * QSTR + np * 16 + a_k8) * 2;
                            ldsm4t(vh[q], sVh + voff);
                            ldsm4t(vl[q], sVl + voff);
                        }
#pragma unroll
                        for (int q = 0; q < 4; q++) {
                            int np = g * 4 + q;
                            mma16816(o[2 * np],     ph[ks2], vh[q]);
                            mma16816(o[2 * np + 1], ph[ks2], vh[q] + 2);
                        }
#pragma unroll
                        for (int q = 0; q < 4; q++) {
                            int np = g * 4 + q;
                            mma16816(o[2 * np],     ph[ks2], vl[q]);
                            mma16816(o[2 * np + 1], ph[ks2], vl[q] + 2);
                        }
                    }
                }
            }
            __syncthreads();
            if (t + 2 < ntiles) load_tile(t + 2, t & 1);
        }

#pragma unroll
        for (int rr = 0; rr < 2; rr++) {
            float inv = 1.0f / l[rr];
            int grow = qrow0 + r0 + rr * 8;
#pragma unroll
            for (int jj = 0; jj < 16; jj++) {
                int col = h * HD + jj * 8 + (lane & 3) * 2;
                *(float2*)&O[(size_t)grow * HID + col] =
                    make_float2(o[jj][rr * 2] * inv, o[jj][rr * 2 + 1] * inv);
            }
        }
    }
}

extern "C" void kernel_launch(void* const* d_in, const int* in_sizes, int n_in,
                              void* d_out, int out_size)
{
    const float* hidden = (const float*)d_in[0];
    const int*   pos    = (const int*)d_in[1];
    const float* Wq     = (const float*)d_in[2];
    const float* Wk     = (const float*)d_in[3];
    const float* Wv     = (const float*)d_in[4];
    const float* Wo     = (const float*)d_in[5];
    float* out = (float*)d_out;

    float *qp, *kp, *vp, *aop;
    __half *ah, *wh, *wh2, *wh3;
    __half *qhp, *khp, *klp, *vhp, *vlp;
    cudaGetSymbolAddress((void**)&qp,  g_Q);
    cudaGetSymbolAddress((void**)&kp,  g_K);
    cudaGetSymbolAddress((void**)&vp,  g_V);
    cudaGetSymbolAddress((void**)&aop, g_AO);
    cudaGetSymbolAddress((void**)&ah,  g_Ah);
    cudaGetSymbolAddress((void**)&wh,  g_Wh);
    cudaGetSymbolAddress((void**)&wh2, g_Wh2);
    cudaGetSymbolAddress((void**)&wh3, g_Wh3);
    cudaGetSymbolAddress((void**)&qhp, g_Qh);
    cudaGetSymbolAddress((void**)&khp, g_Kh);
    cudaGetSymbolAddress((void**)&klp, g_Kl);
    cudaGetSymbolAddress((void**)&vhp, g_Vh);
    cudaGetSymbolAddress((void**)&vlp, g_Vl);

    cudaFuncSetAttribute(gemm1_kernel,
                         cudaFuncAttributeMaxDynamicSharedMemorySize, G1SMEM);
    cudaFuncSetAttribute(flash_mma_kernel,
                         cudaFuncAttributeMaxDynamicSharedMemorySize, FSMEM_TOT);

    const int NA  = S_LEN * HID;
    const int NWQ = HID * HID;
    const int NWK = KVD * HID;

    // (1) act conv, (2) Wq conv, (3) Wk conv, (4) gemm1 Q <- ncu capture
    conv_f16_kernel<<<NA / 4 / 256, 256>>>(hidden, ah, NA);
    conv_f16_kernel<<<NWQ / 4 / 256, 256>>>(Wq, wh, NWQ);
    conv_f16_kernel<<<NWK / 4 / 256, 256>>>(Wk, wh2, NWK);
    gemm1_kernel<<<dim3(HID / 128, S_LEN / 256, 1), 512, G1SMEM>>>(
        ah, wh, qp, wh, qp, HID);

    // K + V projections, fused
    conv_f16_kernel<<<NWK / 4 / 256, 256>>>(Wv, wh3, NWK);
    gemm1_kernel<<<dim3(KVD / 128, S_LEN / 256, 2), 512, G1SMEM>>>(
        ah, wh2, kp, wh3, vp, KVD);

    rope_table_kernel<<<S_LEN * 64 / 256, 256>>>(pos);
    rope_split_kernel<<<S_LEN, 256>>>();
    split_f16_kernel<<<S_LEN * KVD / 4 / 256, 256>>>(vp, vhp, vlp, S_LEN * KVD);

    zero_ctr_kernel<<<1, 1>>>();
    flash_mma_kernel<<<148, 256, FSMEM_TOT>>>(
        qhp, khp, klp, vhp, vlp, aop);

    // O projection, 1-term
    conv_f16_kernel<<<NA / 4 / 256, 256>>>(aop, ah, NA);
    conv_f16_kernel<<<NWQ / 4 / 256, 256>>>(Wo, wh, NWQ);
    gemm1_kernel<<<dim3(HID / 128, S_LEN / 256, 1), 512, G1SMEM>>>(
        ah, wh, out, wh, out, HID);
}

// round 14
// speedup vs baseline: 1.9823x; 1.1381x over previous
#include <cuda_runtime.h>
#include <cuda_fp16.h>
#include <math.h>
#include <stdint.h>

#define S_LEN 2048
#define HID   4096
#define KVD   1024
#define NH    32
#define NKV   8
#define HD    128

__device__ float g_Q[S_LEN * HID];
__device__ float g_K[S_LEN * KVD];
__device__ float g_V[S_LEN * KVD];
__device__ float g_AO[S_LEN * HID];
__device__ __half g_Ah[S_LEN * HID];
__device__ __half g_Wh[HID * HID];
__device__ __half g_Wh2[KVD * HID];
__device__ __half g_Wh3[KVD * HID];
__device__ __half g_Qh[S_LEN * HID];
__device__ __half g_Kh[S_LEN * KVD];
__device__ __half g_Kl[S_LEN * KVD];
__device__ __half g_Vh[S_LEN * KVD];
__device__ __half g_Vl[S_LEN * KVD];
__device__ float g_cos[S_LEN * 64];
__device__ float g_sin[S_LEN * 64];
__device__ unsigned int g_work_ctr;

__device__ __forceinline__ uint32_t smem_u32(const void* p) {
    uint32_t a;
    asm("{ .reg .u64 t; cvta.to.shared.u64 t, %1; cvt.u32.u64 %0, t; }"
        : "=r"(a) : "l"(p));
    return a;
}
__device__ __forceinline__ void ldsm4(uint32_t* r, uint32_t addr) {
    asm volatile("ldmatrix.sync.aligned.m8n8.x4.shared.b16 {%0,%1,%2,%3}, [%4];"
                 : "=r"(r[0]), "=r"(r[1]), "=r"(r[2]), "=r"(r[3]) : "r"(addr));
}
__device__ __forceinline__ void ldsm4t(uint32_t* r, uint32_t addr) {
    asm volatile("ldmatrix.sync.aligned.m8n8.x4.trans.shared.b16 {%0,%1,%2,%3}, [%4];"
                 : "=r"(r[0]), "=r"(r[1]), "=r"(r[2]), "=r"(r[3]) : "r"(addr));
}
__device__ __forceinline__ void mma16816(float* d, const uint32_t* a,
                                         const uint32_t* b) {
    asm volatile(
        "mma.sync.aligned.m16n8k16.row.col.f32.f16.f16.f32 "
        "{%0,%1,%2,%3},{%4,%5,%6,%7},{%8,%9},{%0,%1,%2,%3};"
        : "+f"(d[0]), "+f"(d[1]), "+f"(d[2]), "+f"(d[3])
        : "r"(a[0]), "r"(a[1]), "r"(a[2]), "r"(a[3]), "r"(b[0]), "r"(b[1]));
}
__device__ __forceinline__ void cp_async16(uint32_t dst, const void* src) {
    asm volatile("cp.async.cg.shared.global [%0], [%1], 16;"
                 :: "r"(dst), "l"(src) : "memory");
}

// ---------------------------------------------------------------------------
// fp32 -> fp16 convert / hi+lo split (split used for V only)
// ---------------------------------------------------------------------------
__global__ void conv_f16_kernel(const float* __restrict__ src,
                                __half* __restrict__ dst, int n)
{
    int i = (blockIdx.x * blockDim.x + threadIdx.x) * 4;
    if (i >= n) return;
    float4 v = *(const float4*)(src + i);
    __half2* dp = (__half2*)(dst + i);
    dp[0] = __floats2half2_rn(v.x, v.y);
    dp[1] = __floats2half2_rn(v.z, v.w);
}

__global__ void split_f16_kernel(const float* __restrict__ src,
                                 __half* __restrict__ hi,
                                 __half* __restrict__ lo, int n)
{
    int i = (blockIdx.x * blockDim.x + threadIdx.x) * 4;
    if (i >= n) return;
    float4 v = *(const float4*)(src + i);
    __half h0 = __float2half_rn(v.x);
    __half h1 = __float2half_rn(v.y);
    __half h2 = __float2half_rn(v.z);
    __half h3 = __float2half_rn(v.w);
    __half2* hp = (__half2*)(hi + i);
    __half2* lp = (__half2*)(lo + i);
    hp[0] = __half2(h0, h1); hp[1] = __half2(h2, h3);
    lp[0] = __floats2half2_rn(v.x - __half2float(h0), v.y - __half2float(h1));
    lp[1] = __floats2half2_rn(v.z - __half2float(h2), v.w - __half2float(h3));
}

// ---------------------------------------------------------------------------
// 1-term fp16 GEMM: C = A * B^T (fp32 acc).
// CTA 256x128, 512 threads (16 warps, warp 64x32), BK=64, 3-stage cp.async.
// 64 MMAs/warp per sync (amortize per-tile overhead; fix tensor=41%).
// blockIdx.z selects B/C set (fused launches).
// ---------------------------------------------------------------------------
#define BK 64
#define ASTR 72                       // 64 + 8 pad; 144B row, step 9 mod 8 = 1
#define GT_A (256 * ASTR * 2)         // 36864
#define GT_B (128 * ASTR * 2)         // 18432
#define G1STAGE (GT_A + GT_B)         // 55296
#define G1SMEM (3 * G1STAGE)          // 165888
#define KTILES (HID / BK)             // 64

__global__ __launch_bounds__(512, 1) void gemm1_kernel(
    const __half* __restrict__ A,
    const __half* __restrict__ Bh0, float* __restrict__ C0,
    const __half* __restrict__ Bh1, float* __restrict__ C1, int N)
{
    extern __shared__ char smem[];
    const uint32_t sb = smem_u32(smem);
    const int tid  = threadIdx.x;
    const int wid  = tid >> 5;
    const int lane = tid & 31;
    const int wm   = wid & 3;
    const int wn   = wid >> 2;
    const int m0   = blockIdx.y * 256;
    const int n0   = blockIdx.x * 128;

    const __half* Bh = blockIdx.z ? Bh1 : Bh0;
    float* C = blockIdx.z ? C1 : C0;
    const __half* aSrc = A  + (size_t)m0 * HID;
    const __half* bSrc = Bh + (size_t)n0 * HID;

    auto load_stage = [&](int kt, int stage) {
        const int kc = kt * BK;
        const uint32_t sbase = sb + stage * G1STAGE;
#pragma unroll
        for (int i = 0; i < 4; i++) {             // A: 2048 16B chunks
            int idx = tid + i * 512;
            int row = idx >> 3, kch = idx & 7;
            cp_async16(sbase + (uint32_t)(row * 144 + kch * 16),
                       aSrc + (size_t)row * HID + kc + kch * 8);
        }
#pragma unroll
        for (int i = 0; i < 2; i++) {             // B: 1024 16B chunks
            int idx = tid + i * 512;
            int row = idx >> 3, kch = idx & 7;
            cp_async16(sbase + GT_A + (uint32_t)(row * 144 + kch * 16),
                       bSrc + (size_t)row * HID + kc + kch * 8);
        }
        asm volatile("cp.async.commit_group;" ::: "memory");
    };

    float acc[4][4][4];
#pragma unroll
    for (int i = 0; i < 4; i++)
#pragma unroll
        for (int j = 0; j < 4; j++)
#pragma unroll
            for (int q = 0; q < 4; q++) acc[i][j][q] = 0.0f;

    load_stage(0, 0);
    load_stage(1, 1);

    const int a_la  = lane & 15;
    const int a_k8  = (lane >> 4) << 3;
    const int b_r   = ((lane >> 4) << 3) + (lane & 7);
    const int b_k8  = ((lane >> 3) & 1) << 3;

    for (int kt = 0; kt < KTILES; kt++) {
        if (kt + 1 < KTILES)
            asm volatile("cp.async.wait_group 1;" ::: "memory");
        else
            asm volatile("cp.async.wait_group 0;" ::: "memory");
        __syncthreads();
        if (kt + 2 < KTILES) load_stage(kt + 2, (kt + 2) % 3);

        const uint32_t sbase = sb + (kt % 3) * G1STAGE;
        const uint32_t sA = sbase;
        const uint32_t sB = sbase + GT_A;

#pragma unroll
        for (int k16 = 0; k16 < 4; k16++) {
            uint32_t af[4][4], bf[2][4];
#pragma unroll
            for (int i = 0; i < 4; i++) {
                int arow = wm * 64 + i * 16 + a_la;
                ldsm4(af[i], sA + (uint32_t)(arow * ASTR + k16 * 16 + a_k8) * 2);
            }
#pragma unroll
            for (int jp = 0; jp < 2; jp++) {
                int brow = wn * 32 + jp * 16 + b_r;
                ldsm4(bf[jp], sB + (uint32_t)(brow * ASTR + k16 * 16 + b_k8) * 2);
            }
#pragma unroll
            for (int i = 0; i < 4; i++)
#pragma unroll
                for (int jp = 0; jp < 2; jp++) {
                    mma16816(acc[i][2 * jp],     af[i], bf[jp]);
                    mma16816(acc[i][2 * jp + 1], af[i], bf[jp] + 2);
                }
        }
    }

#pragma unroll
    for (int i = 0; i < 4; i++) {
        int row = m0 + wm * 64 + i * 16 + (lane >> 2);
#pragma unroll
        for (int j = 0; j < 4; j++) {
            int col = n0 + wn * 32 + j * 8 + (lane & 3) * 2;
            *(float2*)&C[(size_t)row * N + col] =
                make_float2(acc[i][j][0], acc[i][j][1]);
            *(float2*)&C[(size_t)(row + 8) * N + col] =
                make_float2(acc[i][j][2], acc[i][j][3]);
        }
    }
}

__global__ void rope_table_kernel(const int* __restrict__ pos)
{
    int idx = blockIdx.x * blockDim.x + threadIdx.x;
    int s = idx >> 6, i = idx & 63;
    double inv = exp(-((double)(2 * i) / 128.0) * 9.210340371976184);
    double ang = (double)pos[s] * inv;
    g_cos[idx] = (float)cos(ang);
    g_sin[idx] = (float)sin(ang);
}

// RoPE + scale(Q) + convert: Q -> hi only; K -> hi + lo.
__global__ void rope_split_kernel()
{
    const int s = blockIdx.x;
    const float qscale = 0.08838834764831845f;
    for (int idx = threadIdx.x; idx < (NH + NKV) * 64; idx += blockDim.x) {
        float c, sn;
        if (idx < NH * 64) {
            int head = idx >> 6, i = idx & 63;
            c = g_cos[s * 64 + i]; sn = g_sin[s * 64 + i];
            size_t base = (size_t)s * HID + head * HD;
            float x0 = g_Q[base + i];
            float x1 = g_Q[base + i + 64];
            g_Qh[base + i]      = __float2half_rn((x0 * c - x1 * sn) * qscale);
            g_Qh[base + i + 64] = __float2half_rn((x1 * c + x0 * sn) * qscale);
        } else {
            int t = idx - NH * 64;
            int head = t >> 6, i = t & 63;
            c = g_cos[s * 64 + i]; sn = g_sin[s * 64 + i];
            size_t base = (size_t)s * KVD + head * HD;
            float x0 = g_K[base + i];
            float x1 = g_K[base + i + 64];
            float y0 = x0 * c - x1 * sn;
            float y1 = x1 * c + x0 * sn;
            __half h0 = __float2half_rn(y0);
            __half h1 = __float2half_rn(y1);
            g_Kh[base + i]      = h0;
            g_Kh[base + i + 64] = h1;
            g_Kl[base + i]      = __float2half_rn(y0 - __half2float(h0));
            g_Kl[base + i + 64] = __float2half_rn(y1 - __half2float(h1));
        }
    }
}

__global__ void zero_ctr_kernel() { g_work_ctr = 0u; }

// ---------------------------------------------------------------------------
// Persistent flash attention.
// QK: Qh*Kh + Qh*Kl (2-term).  PV: Ph*Vh + Ph*Vl (2-term).
// ---------------------------------------------------------------------------
#define QSTR 136
#define FTILE (64 * QSTR * 2)
#define FSTAGE (4 * FTILE)           // Kh, Kl, Vh, Vl
#define FQOFF  (2 * FSTAGE)          // 139264
#define FQSZ   (128 * QSTR * 2)      // 34816
#define FSMEM  (FQOFF + FQSZ)        // 174080
#define FSMEM_TOT (FSMEM + 16)
#define NITEMS (NH * 16)

__global__ __launch_bounds__(256, 1) void flash_mma_kernel(
    const __half* __restrict__ Qh,
    const __half* __restrict__ Kh, const __half* __restrict__ Kl,
    const __half* __restrict__ Vh, const __half* __restrict__ Vl,
    float* __restrict__ O)
{
    extern __shared__ char smem[];
    const uint32_t sb = smem_u32(smem);
    int* sWork = (int*)(smem + FSMEM);
    const int tid = threadIdx.x;
    const int lane = tid & 31;
    const int w = tid >> 5;

    const int a_la = lane & 15;
    const int a_k8 = (lane >> 4) << 3;
    const int b_r  = ((lane >> 4) << 3) + (lane & 7);
    const int b_k8 = ((lane >> 3) & 1) << 3;
    const int r0 = lane >> 2;
    const uint32_t sQh = sb + FQOFF;

    while (true) {
        if (tid == 0) *sWork = (int)atomicAdd(&g_work_ctr, 1u);
        __syncthreads();
        const int j = *sWork;
        if (j >= NITEMS) break;
        const int h  = j & 31;
        const int qb = 15 - (j >> 5);
        const int kvh = h >> 2;
        const int ntiles = 2 * (qb + 1);
        const int qrow0 = qb * 128 + w * 16;

        const __half* qsrc = Qh + (size_t)(qb * 128) * HID + h * HD;
        const __half* tsrc[4] = {
            Kh + (size_t)kvh * HD, Kl + (size_t)kvh * HD,
            Vh + (size_t)kvh * HD, Vl + (size_t)kvh * HD };

#pragma unroll
        for (int i = 0; i < 8; i++) {
            int idx = tid + i * 256;
            int row = idx >> 4, ch = idx & 15;
            cp_async16(sb + FQOFF + (uint32_t)(row * 272 + ch * 16),
                       qsrc + (size_t)row * HID + ch * 8);
        }
        asm volatile("cp.async.commit_group;" ::: "memory");

        auto load_tile = [&](int t, int buf) {
#pragma unroll
            for (int sub = 0; sub < 4; sub++) {
                const __half* src = tsrc[sub];
                const uint32_t tb = sb + buf * FSTAGE + sub * FTILE;
#pragma unroll
                for (int i = 0; i < 4; i++) {
                    int idx = tid + i * 256;
                    int row = idx >> 4, ch = idx & 15;
                    cp_async16(tb + (uint32_t)(row * 272 + ch * 16),
                               src + (size_t)(t * 64 + row) * KVD + ch * 8);
                }
            }
            asm volatile("cp.async.commit_group;" ::: "memory");
        };

        load_tile(0, 0);
        if (ntiles > 1) load_tile(1, 1);

        float m[2] = {-1e30f, -1e30f}, l[2] = {0.0f, 0.0f};
        float o[16][4];
#pragma unroll
        for (int jj = 0; jj < 16; jj++)
#pragma unroll
            for (int q = 0; q < 4; q++) o[jj][q] = 0.0f;

        for (int t = 0; t < ntiles; t++) {
            if (t + 1 < ntiles)
                asm volatile("cp.async.wait_group 1;" ::: "memory");
            else
                asm volatile("cp.async.wait_group 0;" ::: "memory");
            __syncthreads();

            const uint32_t stg = sb + (t & 1) * FSTAGE;
            const uint32_t sKh = stg, sKl = stg + FTILE;
            const uint32_t sVh = stg + 2 * FTILE, sVl = stg + 3 * FTILE;

            const bool skip = (qrow0 + 15) < t * 64;
            if (!skip) {
                float sc[8][4];
#pragma unroll
                for (int nt = 0; nt < 8; nt++)
#pragma unroll
                    for (int q = 0; q < 4; q++) sc[nt][q] = 0.0f;

#pragma unroll
                for (int ks = 0; ks < 8; ks++) {
                    uint32_t aoff = (uint32_t)((w * 16 + a_la) * QSTR + ks * 16 + a_k8) * 2;
                    uint32_t aqh[4];
                    ldsm4(aqh, sQh + aoff);
                    uint32_t bh[4][4], bl[4][4];
#pragma unroll
                    for (int np = 0; np < 4; np++) {
                        uint32_t boff = (uint32_t)((np * 16 + b_r) * QSTR + ks * 16 + b_k8) * 2;
                        ldsm4(bh[np], sKh + boff);
                        ldsm4(bl[np], sKl + boff);
                    }
#pragma unroll
                    for (int np = 0; np < 4; np++) {
                        mma16816(sc[2 * np],     aqh, bh[np]);
                        mma16816(sc[2 * np + 1], aqh, bh[np] + 2);
                    }
#pragma unroll
                    for (int np = 0; np < 4; np++) {
                        mma16816(sc[2 * np],     aqh, bl[np]);
                        mma16816(sc[2 * np + 1], aqh, bl[np] + 2);
                    }
                }

                if (t * 64 + 63 > qrow0) {
#pragma unroll
                    for (int nt = 0; nt < 8; nt++)
#pragma unroll
                        for (int e = 0; e < 4; e++) {
                            int col = t * 64 + nt * 8 + (lane & 3) * 2 + (e & 1);
                            int row = qrow0 + r0 + ((e >> 1) << 3);
                            if (col > row) sc[nt][e] = -1e30f;
                        }
                }

#pragma unroll
                for (int rr = 0; rr < 2; rr++) {
                    float mt = -1e30f;
#pragma unroll
                    for (int nt = 0; nt < 8; nt++)
                        mt = fmaxf(mt, fmaxf(sc[nt][rr * 2], sc[nt][rr * 2 + 1]));
                    mt = fmaxf(mt, __shfl_xor_sync(0xffffffffu, mt, 1));
                    mt = fmaxf(mt, __shfl_xor_sync(0xffffffffu, mt, 2));
                    float mn = fmaxf(m[rr], mt);
                    float alpha = __expf(m[rr] - mn);
                    m[rr] = mn;
                    float sum = 0.0f;
#pragma unroll
                    for (int nt = 0; nt < 8; nt++) {
                        float p0 = __expf(sc[nt][rr * 2]     - mn);
                        float p1 = __expf(sc[nt][rr * 2 + 1] - mn);
                        sc[nt][rr * 2] = p0; sc[nt][rr * 2 + 1] = p1;
                        sum += p0 + p1;
                    }
                    sum += __shfl_xor_sync(0xffffffffu, sum, 1);
                    sum += __shfl_xor_sync(0xffffffffu, sum, 2);
                    l[rr] = l[rr] * alpha + sum;
#pragma unroll
                    for (int jj = 0; jj < 16; jj++) {
                        o[jj][rr * 2]     *= alpha;
                        o[jj][rr * 2 + 1] *= alpha;
                    }
                }

                uint32_t ph[4][4];
#pragma unroll
                for (int ks2 = 0; ks2 < 4; ks2++)
#pragma unroll
                    for (int half = 0; half < 2; half++) {
                        int nt = 2 * ks2 + half;
#pragma unroll
                        for (int rr = 0; rr < 2; rr++) {
                            __half2 hp = __floats2half2_rn(sc[nt][rr * 2],
                                                           sc[nt][rr * 2 + 1]);
                            ph[ks2][half * 2 + rr] = *(uint32_t*)&hp;
                        }
                    }

#pragma unroll
                for (int ks2 = 0; ks2 < 4; ks2++) {
#pragma unroll
                    for (int g = 0; g < 2; g++) {
                        uint32_t vh[4][4], vl[4][4];
#pragma unroll
                        for (int q = 0; q < 4; q++) {
                            int np = g * 4 + q;
                            uint32_t voff = (uint32_t)((ks2 * 16 + a_la) * QSTR + np * 16 + a_k8) * 2;
                            ldsm4t(vh[q], sVh + voff);
                            ldsm4t(vl[q], sVl + voff);
                        }
#pragma unroll
                        for (int q = 0; q < 4; q++) {
                            int np = g * 4 + q;
                            mma16816(o[2 * np],     ph[ks2], vh[q]);
                            mma16816(o[2 * np + 1], ph[ks2], vh[q] + 2);
                        }
#pragma unroll
                        for (int q = 0; q < 4; q++) {
                            int np = g * 4 + q;
                            mma16816(o[2 * np],     ph[ks2], vl[q]);
                            mma16816(o[2 * np + 1], ph[ks2], vl[q] + 2);
                        }
                    }
                }
            }
            __syncthreads();
            if (t + 2 < ntiles) load_tile(t + 2, t & 1);
        }

#pragma unroll
        for (int rr = 0; rr < 2; rr++) {
            float inv = 1.0f / l[rr];
            int grow = qrow0 + r0 + rr * 8;
#pragma unroll
            for (int jj = 0; jj < 16; jj++) {
                int col = h * HD + jj * 8 + (lane & 3) * 2;
                *(float2*)&O[(size_t)grow * HID + col] =
                    make_float2(o[jj][rr * 2] * inv, o[jj][rr * 2 + 1] * inv);
            }
        }
    }
}

extern "C" void kernel_launch(void* const* d_in, const int* in_sizes, int n_in,
                              void* d_out, int out_size)
{
    const float* hidden = (const float*)d_in[0];
    const int*   pos    = (const int*)d_in[1];
    const float* Wq     = (const float*)d_in[2];
    const float* Wk     = (const float*)d_in[3];
    const float* Wv     = (const float*)d_in[4];
    const float* Wo     = (const float*)d_in[5];
    float* out = (float*)d_out;

    float *qp, *kp, *vp, *aop;
    __half *ah, *wh, *wh2, *wh3;
    __half *qhp, *khp, *klp, *vhp, *vlp;
    cudaGetSymbolAddress((void**)&qp,  g_Q);
    cudaGetSymbolAddress((void**)&kp,  g_K);
    cudaGetSymbolAddress((void**)&vp,  g_V);
    cudaGetSymbolAddress((void**)&aop, g_AO);
    cudaGetSymbolAddress((void**)&ah,  g_Ah);
    cudaGetSymbolAddress((void**)&wh,  g_Wh);
    cudaGetSymbolAddress((void**)&wh2, g_Wh2);
    cudaGetSymbolAddress((void**)&wh3, g_Wh3);
    cudaGetSymbolAddress((void**)&qhp, g_Qh);
    cudaGetSymbolAddress((void**)&khp, g_Kh);
    cudaGetSymbolAddress((void**)&klp, g_Kl);
    cudaGetSymbolAddress((void**)&vhp, g_Vh);
    cudaGetSymbolAddress((void**)&vlp, g_Vl);

    cudaFuncSetAttribute(gemm1_kernel,
                         cudaFuncAttributeMaxDynamicSharedMemorySize, G1SMEM);
    cudaFuncSetAttribute(flash_mma_kernel,
                         cudaFuncAttributeMaxDynamicSharedMemorySize, FSMEM_TOT);

    const int NA  = S_LEN * HID;
    const int NWQ = HID * HID;
    const int NWK = KVD * HID;

    // (1) act conv, (2) Wq conv, (3) Wk conv, (4) gemm1 Q <- ncu capture
    conv_f16_kernel<<<NA / 4 / 256, 256>>>(hidden, ah, NA);
    conv_f16_kernel<<<NWQ / 4 / 256, 256>>>(Wq, wh, NWQ);
    conv_f16_kernel<<<NWK / 4 / 256, 256>>>(Wk, wh2, NWK);
    gemm1_kernel<<<dim3(HID / 128, S_LEN / 256, 1), 512, G1SMEM>>>(
        ah, wh, qp, wh, qp, HID);

    // K + V projections, fused
    conv_f16_kernel<<<NWK / 4 / 256, 256>>>(Wv, wh3, NWK);
    gemm1_kernel<<<dim3(KVD / 128, S_LEN / 256, 2), 512, G1SMEM>>>(
        ah, wh2, kp, wh3, vp, KVD);

    rope_table_kernel<<<S_LEN * 64 / 256, 256>>>(pos);
    rope_split_kernel<<<S_LEN, 256>>>();
    split_f16_kernel<<<S_LEN * KVD / 4 / 256, 256>>>(vp, vhp, vlp, S_LEN * KVD);

    zero_ctr_kernel<<<1, 1>>>();
    flash_mma_kernel<<<148, 256, FSMEM_TOT>>>(
        qhp, khp, klp, vhp, vlp, aop);

    // O projection, 1-term
    conv_f16_kernel<<<NA / 4 / 256, 256>>>(aop, ah, NA);
    conv_f16_kernel<<<NWQ / 4 / 256, 256>>>(Wo, wh, NWQ);
    gemm1_kernel<<<dim3(HID / 128, S_LEN / 256, 1), 512, G1SMEM>>>(
        ah, wh, out, wh, out, HID);
}

// round 15
// speedup vs baseline: 2.0187x; 1.0184x over previous
#include <cuda_runtime.h>
#include <cuda_fp16.h>
#include <math.h>
#include <stdint.h>

#define S_LEN 2048
#define HID   4096
#define KVD   1024
#define NH    32
#define NKV   8
#define HD    128

__device__ float g_Q[S_LEN * HID];
__device__ float g_K[S_LEN * KVD];
__device__ float g_V[S_LEN * KVD];
__device__ __half g_Ah[S_LEN * HID];
__device__ __half g_Wh[HID * HID];
__device__ __half g_Wh2[KVD * HID];
__device__ __half g_Wh3[KVD * HID];
__device__ __half g_Qh[S_LEN * HID];
__device__ __half g_Kh[S_LEN * KVD];
__device__ __half g_Kl[S_LEN * KVD];
__device__ __half g_Vh[S_LEN * KVD];
__device__ __half g_Vl[S_LEN * KVD];
__device__ float g_cos[S_LEN * 64];
__device__ float g_sin[S_LEN * 64];
__device__ unsigned int g_work_ctr;

__device__ __forceinline__ uint32_t smem_u32(const void* p) {
    uint32_t a;
    asm("{ .reg .u64 t; cvta.to.shared.u64 t, %1; cvt.u32.u64 %0, t; }"
        : "=r"(a) : "l"(p));
    return a;
}
__device__ __forceinline__ void ldsm4(uint32_t* r, uint32_t addr) {
    asm volatile("ldmatrix.sync.aligned.m8n8.x4.shared.b16 {%0,%1,%2,%3}, [%4];"
                 : "=r"(r[0]), "=r"(r[1]), "=r"(r[2]), "=r"(r[3]) : "r"(addr));
}
__device__ __forceinline__ void ldsm4t(uint32_t* r, uint32_t addr) {
    asm volatile("ldmatrix.sync.aligned.m8n8.x4.trans.shared.b16 {%0,%1,%2,%3}, [%4];"
                 : "=r"(r[0]), "=r"(r[1]), "=r"(r[2]), "=r"(r[3]) : "r"(addr));
}
__device__ __forceinline__ void mma16816(float* d, const uint32_t* a,
                                         const uint32_t* b) {
    asm volatile(
        "mma.sync.aligned.m16n8k16.row.col.f32.f16.f16.f32 "
        "{%0,%1,%2,%3},{%4,%5,%6,%7},{%8,%9},{%0,%1,%2,%3};"
        : "+f"(d[0]), "+f"(d[1]), "+f"(d[2]), "+f"(d[3])
        : "r"(a[0]), "r"(a[1]), "r"(a[2]), "r"(a[3]), "r"(b[0]), "r"(b[1]));
}
__device__ __forceinline__ void cp_async16(uint32_t dst, const void* src) {
    asm volatile("cp.async.cg.shared.global [%0], [%1], 16;"
                 :: "r"(dst), "l"(src) : "memory");
}

// ---------------------------------------------------------------------------
// fp32 -> fp16 convert / hi+lo split (split used for V only)
// ---------------------------------------------------------------------------
__global__ void conv_f16_kernel(const float* __restrict__ src,
                                __half* __restrict__ dst, int n)
{
    int i = (blockIdx.x * blockDim.x + threadIdx.x) * 4;
    if (i >= n) return;
    float4 v = *(const float4*)(src + i);
    __half2* dp = (__half2*)(dst + i);
    dp[0] = __floats2half2_rn(v.x, v.y);
    dp[1] = __floats2half2_rn(v.z, v.w);
}

__global__ void split_f16_kernel(const float* __restrict__ src,
                                 __half* __restrict__ hi,
                                 __half* __restrict__ lo, int n)
{
    int i = (blockIdx.x * blockDim.x + threadIdx.x) * 4;
    if (i >= n) return;
    float4 v = *(const float4*)(src + i);
    __half h0 = __float2half_rn(v.x);
    __half h1 = __float2half_rn(v.y);
    __half h2 = __float2half_rn(v.z);
    __half h3 = __float2half_rn(v.w);
    __half2* hp = (__half2*)(hi + i);
    __half2* lp = (__half2*)(lo + i);
    hp[0] = __half2(h0, h1); hp[1] = __half2(h2, h3);
    lp[0] = __floats2half2_rn(v.x - __half2float(h0), v.y - __half2float(h1));
    lp[1] = __floats2half2_rn(v.z - __half2float(h2), v.w - __half2float(h3));
}

// ---------------------------------------------------------------------------
// 1-term fp16 GEMM: C = A * B^T (fp32 acc).
// CTA 256x128, 256 threads, 8 warps, warp tile 64x64 (4 MMA per ldsm4 ->
// amortize shared-load issue; R8 evidence: 64x64 warp = 55% tensor).
// BK=64, 3-stage cp.async. blockIdx.z selects B/C set.
// ---------------------------------------------------------------------------
#define BK 64
#define ASTR 72                       // 64 + 8 pad; 144B row, step 9 mod 8 = 1
#define GT_A (256 * ASTR * 2)         // 36864
#define GT_B (128 * ASTR * 2)         // 18432
#define G1STAGE (GT_A + GT_B)         // 55296
#define G1SMEM (3 * G1STAGE)          // 165888
#define KTILES (HID / BK)             // 64

__global__ __launch_bounds__(256, 1) void gemm1_kernel(
    const __half* __restrict__ A,
    const __half* __restrict__ Bh0, float* __restrict__ C0,
    const __half* __restrict__ Bh1, float* __restrict__ C1, int N)
{
    extern __shared__ char smem[];
    const uint32_t sb = smem_u32(smem);
    const int tid  = threadIdx.x;
    const int wid  = tid >> 5;
    const int lane = tid & 31;
    const int wm   = wid & 3;                 // 4 m-tiles of 64
    const int wn   = wid >> 2;                // 2 n-tiles of 64
    const int m0   = blockIdx.y * 256;
    const int n0   = blockIdx.x * 128;

    const __half* Bh = blockIdx.z ? Bh1 : Bh0;
    float* C = blockIdx.z ? C1 : C0;
    const __half* aSrc = A  + (size_t)m0 * HID;
    const __half* bSrc = Bh + (size_t)n0 * HID;

    auto load_stage = [&](int kt, int stage) {
        const int kc = kt * BK;
        const uint32_t sbase = sb + stage * G1STAGE;
#pragma unroll
        for (int i = 0; i < 8; i++) {             // A: 2048 16B chunks
            int idx = tid + i * 256;
            int row = idx >> 3, kch = idx & 7;
            cp_async16(sbase + (uint32_t)(row * 144 + kch * 16),
                       aSrc + (size_t)row * HID + kc + kch * 8);
        }
#pragma unroll
        for (int i = 0; i < 4; i++) {             // B: 1024 16B chunks
            int idx = tid + i * 256;
            int row = idx >> 3, kch = idx & 7;
            cp_async16(sbase + GT_A + (uint32_t)(row * 144 + kch * 16),
                       bSrc + (size_t)row * HID + kc + kch * 8);
        }
        asm volatile("cp.async.commit_group;" ::: "memory");
    };

    float acc[4][8][4];                           // 4 m16 x 8 n8 x 4
#pragma unroll
    for (int i = 0; i < 4; i++)
#pragma unroll
        for (int j = 0; j < 8; j++)
#pragma unroll
            for (int q = 0; q < 4; q++) acc[i][j][q] = 0.0f;

    load_stage(0, 0);
    load_stage(1, 1);

    const int a_la  = lane & 15;
    const int a_k8  = (lane >> 4) << 3;
    const int b_r   = ((lane >> 4) << 3) + (lane & 7);
    const int b_k8  = ((lane >> 3) & 1) << 3;

    for (int kt = 0; kt < KTILES; kt++) {
        if (kt + 1 < KTILES)
            asm volatile("cp.async.wait_group 1;" ::: "memory");
        else
            asm volatile("cp.async.wait_group 0;" ::: "memory");
        __syncthreads();
        if (kt + 2 < KTILES) load_stage(kt + 2, (kt + 2) % 3);

        const uint32_t sbase = sb + (kt % 3) * G1STAGE;
        const uint32_t sA = sbase;
        const uint32_t sB = sbase + GT_A;

#pragma unroll
        for (int k16 = 0; k16 < 4; k16++) {
            uint32_t af[4][4], bf[4][4];
#pragma unroll
            for (int i = 0; i < 4; i++) {
                int arow = wm * 64 + i * 16 + a_la;
                ldsm4(af[i], sA + (uint32_t)(arow * ASTR + k16 * 16 + a_k8) * 2);
            }
#pragma unroll
            for (int jp = 0; jp < 4; jp++) {
                int brow = wn * 64 + jp * 16 + b_r;
                ldsm4(bf[jp], sB + (uint32_t)(brow * ASTR + k16 * 16 + b_k8) * 2);
            }
#pragma unroll
            for (int i = 0; i < 4; i++)
#pragma unroll
                for (int jp = 0; jp < 4; jp++) {
                    mma16816(acc[i][2 * jp],     af[i], bf[jp]);
                    mma16816(acc[i][2 * jp + 1], af[i], bf[jp] + 2);
                }
        }
    }

#pragma unroll
    for (int i = 0; i < 4; i++) {
        int row = m0 + wm * 64 + i * 16 + (lane >> 2);
#pragma unroll
        for (int j = 0; j < 8; j++) {
            int col = n0 + wn * 64 + j * 8 + (lane & 3) * 2;
            *(float2*)&C[(size_t)row * N + col] =
                make_float2(acc[i][j][0], acc[i][j][1]);
            *(float2*)&C[(size_t)(row + 8) * N + col] =
                make_float2(acc[i][j][2], acc[i][j][3]);
        }
    }
}

__global__ void rope_table_kernel(const int* __restrict__ pos)
{
    int idx = blockIdx.x * blockDim.x + threadIdx.x;
    int s = idx >> 6, i = idx & 63;
    double inv = exp(-((double)(2 * i) / 128.0) * 9.210340371976184);
    double ang = (double)pos[s] * inv;
    g_cos[idx] = (float)cos(ang);
    g_sin[idx] = (float)sin(ang);
}

// RoPE + scale(Q) + convert: Q -> hi only; K -> hi + lo.
__global__ void rope_split_kernel()
{
    const int s = blockIdx.x;
    const float qscale = 0.08838834764831845f;
    for (int idx = threadIdx.x; idx < (NH + NKV) * 64; idx += blockDim.x) {
        float c, sn;
        if (idx < NH * 64) {
            int head = idx >> 6, i = idx & 63;
            c = g_cos[s * 64 + i]; sn = g_sin[s * 64 + i];
            size_t base = (size_t)s * HID + head * HD;
            float x0 = g_Q[base + i];
            float x1 = g_Q[base + i + 64];
            g_Qh[base + i]      = __float2half_rn((x0 * c - x1 * sn) * qscale);
            g_Qh[base + i + 64] = __float2half_rn((x1 * c + x0 * sn) * qscale);
        } else {
            int t = idx - NH * 64;
            int head = t >> 6, i = t & 63;
            c = g_cos[s * 64 + i]; sn = g_sin[s * 64 + i];
            size_t base = (size_t)s * KVD + head * HD;
            float x0 = g_K[base + i];
            float x1 = g_K[base + i + 64];
            float y0 = x0 * c - x1 * sn;
            float y1 = x1 * c + x0 * sn;
            __half h0 = __float2half_rn(y0);
            __half h1 = __float2half_rn(y1);
            g_Kh[base + i]      = h0;
            g_Kh[base + i + 64] = h1;
            g_Kl[base + i]      = __float2half_rn(y0 - __half2float(h0));
            g_Kl[base + i + 64] = __float2half_rn(y1 - __half2float(h1));
        }
    }
}

__global__ void zero_ctr_kernel() { g_work_ctr = 0u; }

// ---------------------------------------------------------------------------
// Persistent flash attention.
// QK: Qh*Kh + Qh*Kl.  PV: Ph*Vh + Ph*Vl.
// Epilogue writes fp16 directly into g_Ah (O-projection input).
// ---------------------------------------------------------------------------
#define QSTR 136
#define FTILE (64 * QSTR * 2)
#define FSTAGE (4 * FTILE)           // Kh, Kl, Vh, Vl
#define FQOFF  (2 * FSTAGE)          // 139264
#define FQSZ   (128 * QSTR * 2)      // 34816
#define FSMEM  (FQOFF + FQSZ)        // 174080
#define FSMEM_TOT (FSMEM + 16)
#define NITEMS (NH * 16)

__global__ __launch_bounds__(256, 1) void flash_mma_kernel(
    const __half* __restrict__ Qh,
    const __half* __restrict__ Kh, const __half* __restrict__ Kl,
    const __half* __restrict__ Vh, const __half* __restrict__ Vl,
    __half* __restrict__ Oh)
{
    extern __shared__ char smem[];
    const uint32_t sb = smem_u32(smem);
    int* sWork = (int*)(smem + FSMEM);
    const int tid = threadIdx.x;
    const int lane = tid & 31;
    const int w = tid >> 5;

    const int a_la = lane & 15;
    const int a_k8 = (lane >> 4) << 3;
    const int b_r  = ((lane >> 4) << 3) + (lane & 7);
    const int b_k8 = ((lane >> 3) & 1) << 3;
    const int r0 = lane >> 2;
    const uint32_t sQh = sb + FQOFF;

    while (true) {
        if (tid == 0) *sWork = (int)atomicAdd(&g_work_ctr, 1u);
        __syncthreads();
        const int j = *sWork;
        if (j >= NITEMS) break;
        const int h  = j & 31;
        const int qb = 15 - (j >> 5);
        const int kvh = h >> 2;
        const int ntiles = 2 * (qb + 1);
        const int qrow0 = qb * 128 + w * 16;

        const __half* qsrc = Qh + (size_t)(qb * 128) * HID + h * HD;
        const __half* tsrc[4] = {
            Kh + (size_t)kvh * HD, Kl + (size_t)kvh * HD,
            Vh + (size_t)kvh * HD, Vl + (size_t)kvh * HD };

#pragma unroll
        for (int i = 0; i < 8; i++) {
            int idx = tid + i * 256;
            int row = idx >> 4, ch = idx & 15;
            cp_async16(sb + FQOFF + (uint32_t)(row * 272 + ch * 16),
                       qsrc + (size_t)row * HID + ch * 8);
        }
        asm volatile("cp.async.commit_group;" ::: "memory");

        auto load_tile = [&](int t, int buf) {
#pragma unroll
            for (int sub = 0; sub < 4; sub++) {
                const __half* src = tsrc[sub];
                const uint32_t tb = sb + buf * FSTAGE + sub * FTILE;
#pragma unroll
                for (int i = 0; i < 4; i++) {
                    int idx = tid + i * 256;
                    int row = idx >> 4, ch = idx & 15;
                    cp_async16(tb + (uint32_t)(row * 272 + ch * 16),
                               src + (size_t)(t * 64 + row) * KVD + ch * 8);
                }
            }
            asm volatile("cp.async.commit_group;" ::: "memory");
        };

        load_tile(0, 0);
        if (ntiles > 1) load_tile(1, 1);

        float m[2] = {-1e30f, -1e30f}, l[2] = {0.0f, 0.0f};
        float o[16][4];
#pragma unroll
        for (int jj = 0; jj < 16; jj++)
#pragma unroll
            for (int q = 0; q < 4; q++) o[jj][q] = 0.0f;

        for (int t = 0; t < ntiles; t++) {
            if (t + 1 < ntiles)
                asm volatile("cp.async.wait_group 1;" ::: "memory");
            else
                asm volatile("cp.async.wait_group 0;" ::: "memory");
            __syncthreads();

            const uint32_t stg = sb + (t & 1) * FSTAGE;
            const uint32_t sKh = stg, sKl = stg + FTILE;
            const uint32_t sVh = stg + 2 * FTILE, sVl = stg + 3 * FTILE;

            const bool skip = (qrow0 + 15) < t * 64;
            if (!skip) {
                float sc[8][4];
#pragma unroll
                for (int nt = 0; nt < 8; nt++)
#pragma unroll
                    for (int q = 0; q < 4; q++) sc[nt][q] = 0.0f;

#pragma unroll
                for (int ks = 0; ks < 8; ks++) {
                    uint32_t aoff = (uint32_t)((w * 16 + a_la) * QSTR + ks * 16 + a_k8) * 2;
                    uint32_t aqh[4];
                    ldsm4(aqh, sQh + aoff);
                    uint32_t bh[4][4], bl[4][4];
#pragma unroll
                    for (int np = 0; np < 4; np++) {
                        uint32_t boff = (uint32_t)((np * 16 + b_r) * QSTR + ks * 16 + b_k8) * 2;
                        ldsm4(bh[np], sKh + boff);
                        ldsm4(bl[np], sKl + boff);
                    }
#pragma unroll
                    for (int np = 0; np < 4; np++) {
                        mma16816(sc[2 * np],     aqh, bh[np]);
                        mma16816(sc[2 * np + 1], aqh, bh[np] + 2);
                    }
#pragma unroll
                    for (int np = 0; np < 4; np++) {
                        mma16816(sc[2 * np],     aqh, bl[np]);
                        mma16816(sc[2 * np + 1], aqh, bl[np] + 2);
                    }
                }

                if (t * 64 + 63 > qrow0) {
#pragma unroll
                    for (int nt = 0; nt < 8; nt++)
#pragma unroll
                        for (int e = 0; e < 4; e++) {
                            int col = t * 64 + nt * 8 + (lane & 3) * 2 + (e & 1);
                            int row = qrow0 + r0 + ((e >> 1) << 3);
                            if (col > row) sc[nt][e] = -1e30f;
                        }
                }

#pragma unroll
                for (int rr = 0; rr < 2; rr++) {
                    float mt = -1e30f;
#pragma unroll
                    for (int nt = 0; nt < 8; nt++)
                        mt = fmaxf(mt, fmaxf(sc[nt][rr * 2], sc[nt][rr * 2 + 1]));
                    mt = fmaxf(mt, __shfl_xor_sync(0xffffffffu, mt, 1));
                    mt = fmaxf(mt, __shfl_xor_sync(0xffffffffu, mt, 2));
                    float mn = fmaxf(m[rr], mt);
                    float alpha = __expf(m[rr] - mn);
                    m[rr] = mn;
                    float sum = 0.0f;
#pragma unroll
                    for (int nt = 0; nt < 8; nt++) {
                        float p0 = __expf(sc[nt][rr * 2]     - mn);
                        float p1 = __expf(sc[nt][rr * 2 + 1] - mn);
                        sc[nt][rr * 2] = p0; sc[nt][rr * 2 + 1] = p1;
                        sum += p0 + p1;
                    }
                    sum += __shfl_xor_sync(0xffffffffu, sum, 1);
                    sum += __shfl_xor_sync(0xffffffffu, sum, 2);
                    l[rr] = l[rr] * alpha + sum;
#pragma unroll
                    for (int jj = 0; jj < 16; jj++) {
                        o[jj][rr * 2]     *= alpha;
                        o[jj][rr * 2 + 1] *= alpha;
                    }
                }

                uint32_t ph[4][4];
#pragma unroll
                for (int ks2 = 0; ks2 < 4; ks2++)
#pragma unroll
                    for (int half = 0; half < 2; half++) {
                        int nt = 2 * ks2 + half;
#pragma unroll
                        for (int rr = 0; rr < 2; rr++) {
                            __half2 hp = __floats2half2_rn(sc[nt][rr * 2],
                                                           sc[nt][rr * 2 + 1]);
                            ph[ks2][half * 2 + rr] = *(uint32_t*)&hp;
                        }
                    }

#pragma unroll
                for (int ks2 = 0; ks2 < 4; ks2++) {
#pragma unroll
                    for (int g = 0; g < 2; g++) {
                        uint32_t vh[4][4], vl[4][4];
#pragma unroll
                        for (int q = 0; q < 4; q++) {
                            int np = g * 4 + q;
                            uint32_t voff = (uint32_t)((ks2 * 16 + a_la) * QSTR + np * 16 + a_k8) * 2;
                            ldsm4t(vh[q], sVh + voff);
                            ldsm4t(vl[q], sVl + voff);
                        }
#pragma unroll
                        for (int q = 0; q < 4; q++) {
                            int np = g * 4 + q;
                            mma16816(o[2 * np],     ph[ks2], vh[q]);
                            mma16816(o[2 * np + 1], ph[ks2], vh[q] + 2);
                        }
#pragma unroll
                        for (int q = 0; q < 4; q++) {
                            int np = g * 4 + q;
                            mma16816(o[2 * np],     ph[ks2], vl[q]);
                            mma16816(o[2 * np + 1], ph[ks2], vl[q] + 2);
                        }
                    }
                }
            }
            __syncthreads();
            if (t + 2 < ntiles) load_tile(t + 2, t & 1);
        }

        // epilogue: normalize, convert to fp16, write directly to O-proj input
#pragma unroll
        for (int rr = 0; rr < 2; rr++) {
            float inv = 1.0f / l[rr];
            int grow = qrow0 + r0 + rr * 8;
#pragma unroll
            for (int jj = 0; jj < 16; jj++) {
                int col = h * HD + jj * 8 + (lane & 3) * 2;
                __half2 hv = __floats2half2_rn(o[jj][rr * 2] * inv,
                                               o[jj][rr * 2 + 1] * inv);
                *(__half2*)&Oh[(size_t)grow * HID + col] = hv;
            }
        }
    }
}

extern "C" void kernel_launch(void* const* d_in, const int* in_sizes, int n_in,
                              void* d_out, int out_size)
{
    const float* hidden = (const float*)d_in[0];
    const int*   pos    = (const int*)d_in[1];
    const float* Wq     = (const float*)d_in[2];
    const float* Wk     = (const float*)d_in[3];
    const float* Wv     = (const float*)d_in[4];
    const float* Wo     = (const float*)d_in[5];
    float* out = (float*)d_out;

    float *qp, *kp, *vp;
    __half *ah, *wh, *wh2, *wh3;
    __half *qhp, *khp, *klp, *vhp, *vlp;
    cudaGetSymbolAddress((void**)&qp,  g_Q);
    cudaGetSymbolAddress((void**)&kp,  g_K);
    cudaGetSymbolAddress((void**)&vp,  g_V);
    cudaGetSymbolAddress((void**)&ah,  g_Ah);
    cudaGetSymbolAddress((void**)&wh,  g_Wh);
    cudaGetSymbolAddress((void**)&wh2, g_Wh2);
    cudaGetSymbolAddress((void**)&wh3, g_Wh3);
    cudaGetSymbolAddress((void**)&qhp, g_Qh);
    cudaGetSymbolAddress((void**)&khp, g_Kh);
    cudaGetSymbolAddress((void**)&klp, g_Kl);
    cudaGetSymbolAddress((void**)&vhp, g_Vh);
    cudaGetSymbolAddress((void**)&vlp, g_Vl);

    cudaFuncSetAttribute(gemm1_kernel,
                         cudaFuncAttributeMaxDynamicSharedMemorySize, G1SMEM);
    cudaFuncSetAttribute(flash_mma_kernel,
                         cudaFuncAttributeMaxDynamicSharedMemorySize, FSMEM_TOT);

    const int NA  = S_LEN * HID;
    const int NWQ = HID * HID;
    const int NWK = KVD * HID;

    // (1) act conv, (2) Wq conv, (3) Wk conv, (4) gemm1 Q <- ncu capture
    conv_f16_kernel<<<NA / 4 / 256, 256>>>(hidden, ah, NA);
    conv_f16_kernel<<<NWQ / 4 / 256, 256>>>(Wq, wh, NWQ);
    conv_f16_kernel<<<NWK / 4 / 256, 256>>>(Wk, wh2, NWK);
    gemm1_kernel<<<dim3(HID / 128, S_LEN / 256, 1), 256, G1SMEM>>>(
        ah, wh, qp, wh, qp, HID);

    // K + V projections, fused
    conv_f16_kernel<<<NWK / 4 / 256, 256>>>(Wv, wh3, NWK);
    gemm1_kernel<<<dim3(KVD / 128, S_LEN / 256, 2), 256, G1SMEM>>>(
        ah, wh2, kp, wh3, vp, KVD);

    rope_table_kernel<<<S_LEN * 64 / 256, 256>>>(pos);
    rope_split_kernel<<<S_LEN, 256>>>();
    split_f16_kernel<<<S_LEN * KVD / 4 / 256, 256>>>(vp, vhp, vlp, S_LEN * KVD);

    zero_ctr_kernel<<<1, 1>>>();
    flash_mma_kernel<<<148, 256, FSMEM_TOT>>>(
        qhp, khp, klp, vhp, vlp, ah);     // writes fp16 O-proj input directly

    // O projection (input g_Ah written by flash)
    conv_f16_kernel<<<NWQ / 4 / 256, 256>>>(Wo, wh, NWQ);
    gemm1_kernel<<<dim3(HID / 128, S_LEN / 256, 1), 256, G1SMEM>>>(
        ah, wh, out, wh, out, HID);
}

// round 16
// speedup vs baseline: 2.0998x; 1.0402x over previous
#include <cuda_runtime.h>
#include <cuda_fp16.h>
#include <math.h>
#include <stdint.h>

#define S_LEN 2048
#define HID   4096
#define KVD   1024
#define NH    32
#define NKV   8
#define HD    128

__device__ float g_Q[S_LEN * HID];
__device__ float g_K[S_LEN * KVD];
__device__ float g_V[S_LEN * KVD];
__device__ __half g_Ah[S_LEN * HID];
__device__ __half g_Wh[HID * HID];
__device__ __half g_Wh2[KVD * HID];
__device__ __half g_Wh3[KVD * HID];
__device__ __half g_Qh[S_LEN * HID];
__device__ __half g_Kh[S_LEN * KVD];
__device__ __half g_Kl[S_LEN * KVD];
__device__ __half g_Vh[S_LEN * KVD];
__device__ __half g_Vl[S_LEN * KVD];
__device__ float g_cos[S_LEN * 64];
__device__ float g_sin[S_LEN * 64];
__device__ unsigned int g_work_ctr;

__device__ __forceinline__ uint32_t smem_u32(const void* p) {
    uint32_t a;
    asm("{ .reg .u64 t; cvta.to.shared.u64 t, %1; cvt.u32.u64 %0, t; }"
        : "=r"(a) : "l"(p));
    return a;
}
__device__ __forceinline__ void ldsm4(uint32_t* r, uint32_t addr) {
    asm volatile("ldmatrix.sync.aligned.m8n8.x4.shared.b16 {%0,%1,%2,%3}, [%4];"
                 : "=r"(r[0]), "=r"(r[1]), "=r"(r[2]), "=r"(r[3]) : "r"(addr));
}
__device__ __forceinline__ void ldsm4t(uint32_t* r, uint32_t addr) {
    asm volatile("ldmatrix.sync.aligned.m8n8.x4.trans.shared.b16 {%0,%1,%2,%3}, [%4];"
                 : "=r"(r[0]), "=r"(r[1]), "=r"(r[2]), "=r"(r[3]) : "r"(addr));
}
__device__ __forceinline__ void mma16816(float* d, const uint32_t* a,
                                         const uint32_t* b) {
    asm volatile(
        "mma.sync.aligned.m16n8k16.row.col.f32.f16.f16.f32 "
        "{%0,%1,%2,%3},{%4,%5,%6,%7},{%8,%9},{%0,%1,%2,%3};"
        : "+f"(d[0]), "+f"(d[1]), "+f"(d[2]), "+f"(d[3])
        : "r"(a[0]), "r"(a[1]), "r"(a[2]), "r"(a[3]), "r"(b[0]), "r"(b[1]));
}
__device__ __forceinline__ void cp_async16(uint32_t dst, const void* src) {
    asm volatile("cp.async.cg.shared.global [%0], [%1], 16;"
                 :: "r"(dst), "l"(src) : "memory");
}

// ---------------------------------------------------------------------------
// fp32 -> fp16 convert / hi+lo split (split used for V only)
// ---------------------------------------------------------------------------
__global__ void conv_f16_kernel(const float* __restrict__ src,
                                __half* __restrict__ dst, int n)
{
    int i = (blockIdx.x * blockDim.x + threadIdx.x) * 4;
    if (i >= n) return;
    float4 v = *(const float4*)(src + i);
    __half2* dp = (__half2*)(dst + i);
    dp[0] = __floats2half2_rn(v.x, v.y);
    dp[1] = __floats2half2_rn(v.z, v.w);
}

__global__ void split_f16_kernel(const float* __restrict__ src,
                                 __half* __restrict__ hi,
                                 __half* __restrict__ lo, int n)
{
    int i = (blockIdx.x * blockDim.x + threadIdx.x) * 4;
    if (i >= n) return;
    float4 v = *(const float4*)(src + i);
    __half h0 = __float2half_rn(v.x);
    __half h1 = __float2half_rn(v.y);
    __half h2 = __float2half_rn(v.z);
    __half h3 = __float2half_rn(v.w);
    __half2* hp = (__half2*)(hi + i);
    __half2* lp = (__half2*)(lo + i);
    hp[0] = __half2(h0, h1); hp[1] = __half2(h2, h3);
    lp[0] = __floats2half2_rn(v.x - __half2float(h0), v.y - __half2float(h1));
    lp[1] = __floats2half2_rn(v.z - __half2float(h2), v.w - __half2float(h3));
}

// ---------------------------------------------------------------------------
// 1-term fp16 GEMM: C = A * B^T (fp32 acc).
// CTA 128x128, 256 threads (8 warps, warp 64x32), BK=64, 3-stage cp.async.
// smem 110592 B + <=128 regs -> 2 CTAs/SM: independent barrier phases
// interleave and fill each other's tensor-pipe bubbles.
// blockIdx.z selects B/C set (fused launches).
// ---------------------------------------------------------------------------
#define BK 64
#define ASTR 72                       // 64 + 8 pad; 144B row, step 9 mod 8 = 1
#define GT_A (128 * ASTR * 2)         // 18432
#define GT_B (128 * ASTR * 2)         // 18432
#define G1STAGE (GT_A + GT_B)         // 36864
#define G1SMEM (3 * G1STAGE)          // 110592
#define KTILES (HID / BK)             // 64

__global__ __launch_bounds__(256, 2) void gemm1_kernel(
    const __half* __restrict__ A,
    const __half* __restrict__ Bh0, float* __restrict__ C0,
    const __half* __restrict__ Bh1, float* __restrict__ C1, int N)
{
    extern __shared__ char smem[];
    const uint32_t sb = smem_u32(smem);
    const int tid  = threadIdx.x;
    const int wid  = tid >> 5;
    const int lane = tid & 31;
    const int wm   = wid & 1;                 // 2 m-tiles of 64
    const int wn   = wid >> 1;                // 4 n-tiles of 32
    const int m0   = blockIdx.y * 128;
    const int n0   = blockIdx.x * 128;

    const __half* Bh = blockIdx.z ? Bh1 : Bh0;
    float* C = blockIdx.z ? C1 : C0;
    const __half* aSrc = A  + (size_t)m0 * HID;
    const __half* bSrc = Bh + (size_t)n0 * HID;

    auto load_stage = [&](int kt, int stage) {
        const int kc = kt * BK;
        const uint32_t sbase = sb + stage * G1STAGE;
#pragma unroll
        for (int i = 0; i < 4; i++) {             // A: 1024 16B chunks
            int idx = tid + i * 256;
            int row = idx >> 3, kch = idx & 7;
            cp_async16(sbase + (uint32_t)(row * 144 + kch * 16),
                       aSrc + (size_t)row * HID + kc + kch * 8);
        }
#pragma unroll
        for (int i = 0; i < 4; i++) {             // B: 1024 16B chunks
            int idx = tid + i * 256;
            int row = idx >> 3, kch = idx & 7;
            cp_async16(sbase + GT_A + (uint32_t)(row * 144 + kch * 16),
                       bSrc + (size_t)row * HID + kc + kch * 8);
        }
        asm volatile("cp.async.commit_group;" ::: "memory");
    };

    float acc[4][4][4];                           // 4 m16 x 4 n8 x 4
#pragma unroll
    for (int i = 0; i < 4; i++)
#pragma unroll
        for (int j = 0; j < 4; j++)
#pragma unroll
            for (int q = 0; q < 4; q++) acc[i][j][q] = 0.0f;

    load_stage(0, 0);
    load_stage(1, 1);

    const int a_la  = lane & 15;
    const int a_k8  = (lane >> 4) << 3;
    const int b_r   = ((lane >> 4) << 3) + (lane & 7);
    const int b_k8  = ((lane >> 3) & 1) << 3;

    for (int kt = 0; kt < KTILES; kt++) {
        if (kt + 1 < KTILES)
            asm volatile("cp.async.wait_group 1;" ::: "memory");
        else
            asm volatile("cp.async.wait_group 0;" ::: "memory");
        __syncthreads();
        if (kt + 2 < KTILES) load_stage(kt + 2, (kt + 2) % 3);

        const uint32_t sbase = sb + (kt % 3) * G1STAGE;
        const uint32_t sA = sbase;
        const uint32_t sB = sbase + GT_A;

#pragma unroll
        for (int k16 = 0; k16 < 4; k16++) {
            uint32_t af[4][4], bf[2][4];
#pragma unroll
            for (int i = 0; i < 4; i++) {
                int arow = wm * 64 + i * 16 + a_la;
                ldsm4(af[i], sA + (uint32_t)(arow * ASTR + k16 * 16 + a_k8) * 2);
            }
#pragma unroll
            for (int jp = 0; jp < 2; jp++) {
                int brow = wn * 32 + jp * 16 + b_r;
                ldsm4(bf[jp], sB + (uint32_t)(brow * ASTR + k16 * 16 + b_k8) * 2);
            }
#pragma unroll
            for (int i = 0; i < 4; i++)
#pragma unroll
                for (int jp = 0; jp < 2; jp++) {
                    mma16816(acc[i][2 * jp],     af[i], bf[jp]);
                    mma16816(acc[i][2 * jp + 1], af[i], bf[jp] + 2);
                }
        }
    }

#pragma unroll
    for (int i = 0; i < 4; i++) {
        int row = m0 + wm * 64 + i * 16 + (lane >> 2);
#pragma unroll
        for (int j = 0; j < 4; j++) {
            int col = n0 + wn * 32 + j * 8 + (lane & 3) * 2;
            *(float2*)&C[(size_t)row * N + col] =
                make_float2(acc[i][j][0], acc[i][j][1]);
            *(float2*)&C[(size_t)(row + 8) * N + col] =
                make_float2(acc[i][j][2], acc[i][j][3]);
        }
    }
}

__global__ void rope_table_kernel(const int* __restrict__ pos)
{
    int idx = blockIdx.x * blockDim.x + threadIdx.x;
    int s = idx >> 6, i = idx & 63;
    double inv = exp(-((double)(2 * i) / 128.0) * 9.210340371976184);
    double ang = (double)pos[s] * inv;
    g_cos[idx] = (float)cos(ang);
    g_sin[idx] = (float)sin(ang);
}

// RoPE + scale(Q) + convert: Q -> hi only; K -> hi + lo.
__global__ void rope_split_kernel()
{
    const int s = blockIdx.x;
    const float qscale = 0.08838834764831845f;
    for (int idx = threadIdx.x; idx < (NH + NKV) * 64; idx += blockDim.x) {
        float c, sn;
        if (idx < NH * 64) {
            int head = idx >> 6, i = idx & 63;
            c = g_cos[s * 64 + i]; sn = g_sin[s * 64 + i];
            size_t base = (size_t)s * HID + head * HD;
            float x0 = g_Q[base + i];
            float x1 = g_Q[base + i + 64];
            g_Qh[base + i]      = __float2half_rn((x0 * c - x1 * sn) * qscale);
            g_Qh[base + i + 64] = __float2half_rn((x1 * c + x0 * sn) * qscale);
        } else {
            int t = idx - NH * 64;
            int head = t >> 6, i = t & 63;
            c = g_cos[s * 64 + i]; sn = g_sin[s * 64 + i];
            size_t base = (size_t)s * KVD + head * HD;
            float x0 = g_K[base + i];
            float x1 = g_K[base + i + 64];
            float y0 = x0 * c - x1 * sn;
            float y1 = x1 * c + x0 * sn;
            __half h0 = __float2half_rn(y0);
            __half h1 = __float2half_rn(y1);
            g_Kh[base + i]      = h0;
            g_Kh[base + i + 64] = h1;
            g_Kl[base + i]      = __float2half_rn(y0 - __half2float(h0));
            g_Kl[base + i + 64] = __float2half_rn(y1 - __half2float(h1));
        }
    }
}

__global__ void zero_ctr_kernel() { g_work_ctr = 0u; }

// ---------------------------------------------------------------------------
// Persistent flash attention.
// QK: Qh*Kh + Qh*Kl.  PV: Ph*Vh + Ph*Vl.
// Epilogue writes fp16 directly into g_Ah (O-projection input).
// ---------------------------------------------------------------------------
#define QSTR 136
#define FTILE (64 * QSTR * 2)
#define FSTAGE (4 * FTILE)           // Kh, Kl, Vh, Vl
#define FQOFF  (2 * FSTAGE)          // 139264
#define FQSZ   (128 * QSTR * 2)      // 34816
#define FSMEM  (FQOFF + FQSZ)        // 174080
#define FSMEM_TOT (FSMEM + 16)
#define NITEMS (NH * 16)

__global__ __launch_bounds__(256, 1) void flash_mma_kernel(
    const __half* __restrict__ Qh,
    const __half* __restrict__ Kh, const __half* __restrict__ Kl,
    const __half* __restrict__ Vh, const __half* __restrict__ Vl,
    __half* __restrict__ Oh)
{
    extern __shared__ char smem[];
    const uint32_t sb = smem_u32(smem);
    int* sWork = (int*)(smem + FSMEM);
    const int tid = threadIdx.x;
    const int lane = tid & 31;
    const int w = tid >> 5;

    const int a_la = lane & 15;
    const int a_k8 = (lane >> 4) << 3;
    const int b_r  = ((lane >> 4) << 3) + (lane & 7);
    const int b_k8 = ((lane >> 3) & 1) << 3;
    const int r0 = lane >> 2;
    const uint32_t sQh = sb + FQOFF;

    while (true) {
        if (tid == 0) *sWork = (int)atomicAdd(&g_work_ctr, 1u);
        __syncthreads();
        const int j = *sWork;
        if (j >= NITEMS) break;
        const int h  = j & 31;
        const int qb = 15 - (j >> 5);
        const int kvh = h >> 2;
        const int ntiles = 2 * (qb + 1);
        const int qrow0 = qb * 128 + w * 16;

        const __half* qsrc = Qh + (size_t)(qb * 128) * HID + h * HD;
        const __half* tsrc[4] = {
            Kh + (size_t)kvh * HD, Kl + (size_t)kvh * HD,
            Vh + (size_t)kvh * HD, Vl + (size_t)kvh * HD };

#pragma unroll
        for (int i = 0; i < 8; i++) {
            int idx = tid + i * 256;
            int row = idx >> 4, ch = idx & 15;
            cp_async16(sb + FQOFF + (uint32_t)(row * 272 + ch * 16),
                       qsrc + (size_t)row * HID + ch * 8);
        }
        asm volatile("cp.async.commit_group;" ::: "memory");

        auto load_tile = [&](int t, int buf) {
#pragma unroll
            for (int sub = 0; sub < 4; sub++) {
                const __half* src = tsrc[sub];
                const uint32_t tb = sb + buf * FSTAGE + sub * FTILE;
#pragma unroll
                for (int i = 0; i < 4; i++) {
                    int idx = tid + i * 256;
                    int row = idx >> 4, ch = idx & 15;
                    cp_async16(tb + (uint32_t)(row * 272 + ch * 16),
                               src + (size_t)(t * 64 + row) * KVD + ch * 8);
                }
            }
            asm volatile("cp.async.commit_group;" ::: "memory");
        };

        load_tile(0, 0);
        if (ntiles > 1) load_tile(1, 1);

        float m[2] = {-1e30f, -1e30f}, l[2] = {0.0f, 0.0f};
        float o[16][4];
#pragma unroll
        for (int jj = 0; jj < 16; jj++)
#pragma unroll
            for (int q = 0; q < 4; q++) o[jj][q] = 0.0f;

        for (int t = 0; t < ntiles; t++) {
            if (t + 1 < ntiles)
                asm volatile("cp.async.wait_group 1;" ::: "memory");
            else
                asm volatile("cp.async.wait_group 0;" ::: "memory");
            __syncthreads();

            const uint32_t stg = sb + (t & 1) * FSTAGE;
            const uint32_t sKh = stg, sKl = stg + FTILE;
            const uint32_t sVh = stg + 2 * FTILE, sVl = stg + 3 * FTILE;

            const bool skip = (qrow0 + 15) < t * 64;
            if (!skip) {
                float sc[8][4];
#pragma unroll
                for (int nt = 0; nt < 8; nt++)
#pragma unroll
                    for (int q = 0; q < 4; q++) sc[nt][q] = 0.0f;

#pragma unroll
                for (int ks = 0; ks < 8; ks++) {
                    uint32_t aoff = (uint32_t)((w * 16 + a_la) * QSTR + ks * 16 + a_k8) * 2;
                    uint32_t aqh[4];
                    ldsm4(aqh, sQh + aoff);
                    uint32_t bh[4][4], bl[4][4];
#pragma unroll
                    for (int np = 0; np < 4; np++) {
                        uint32_t boff = (uint32_t)((np * 16 + b_r) * QSTR + ks * 16 + b_k8) * 2;
                        ldsm4(bh[np], sKh + boff);
                        ldsm4(bl[np], sKl + boff);
                    }
#pragma unroll
                    for (int np = 0; np < 4; np++) {
                        mma16816(sc[2 * np],     aqh, bh[np]);
                        mma16816(sc[2 * np + 1], aqh, bh[np] + 2);
                    }
#pragma unroll
                    for (int np = 0; np < 4; np++) {
                        mma16816(sc[2 * np],     aqh, bl[np]);
                        mma16816(sc[2 * np + 1], aqh, bl[np] + 2);
                    }
                }

                if (t * 64 + 63 > qrow0) {
#pragma unroll
                    for (int nt = 0; nt < 8; nt++)
#pragma unroll
                        for (int e = 0; e < 4; e++) {
                            int col = t * 64 + nt * 8 + (lane & 3) * 2 + (e & 1);
                            int row = qrow0 + r0 + ((e >> 1) << 3);
                            if (col > row) sc[nt][e] = -1e30f;
                        }
                }

#pragma unroll
                for (int rr = 0; rr < 2; rr++) {
                    float mt = -1e30f;
#pragma unroll
                    for (int nt = 0; nt < 8; nt++)
                        mt = fmaxf(mt, fmaxf(sc[nt][rr * 2], sc[nt][rr * 2 + 1]));
                    mt = fmaxf(mt, __shfl_xor_sync(0xffffffffu, mt, 1));
                    mt = fmaxf(mt, __shfl_xor_sync(0xffffffffu, mt, 2));
                    float mn = fmaxf(m[rr], mt);
                    float alpha = __expf(m[rr] - mn);
                    m[rr] = mn;
                    float sum = 0.0f;
#pragma unroll
                    for (int nt = 0; nt < 8; nt++) {
                        float p0 = __expf(sc[nt][rr * 2]     - mn);
                        float p1 = __expf(sc[nt][rr * 2 + 1] - mn);
                        sc[nt][rr * 2] = p0; sc[nt][rr * 2 + 1] = p1;
                        sum += p0 + p1;
                    }
                    sum += __shfl_xor_sync(0xffffffffu, sum, 1);
                    sum += __shfl_xor_sync(0xffffffffu, sum, 2);
                    l[rr] = l[rr] * alpha + sum;
#pragma unroll
                    for (int jj = 0; jj < 16; jj++) {
                        o[jj][rr * 2]     *= alpha;
                        o[jj][rr * 2 + 1] *= alpha;
                    }
                }

                uint32_t ph[4][4];
#pragma unroll
                for (int ks2 = 0; ks2 < 4; ks2++)
#pragma unroll
                    for (int half = 0; half < 2; half++) {
                        int nt = 2 * ks2 + half;
#pragma unroll
                        for (int rr = 0; rr < 2; rr++) {
                            __half2 hp = __floats2half2_rn(sc[nt][rr * 2],
                                                           sc[nt][rr * 2 + 1]);
                            ph[ks2][half * 2 + rr] = *(uint32_t*)&hp;
                        }
                    }

#pragma unroll
                for (int ks2 = 0; ks2 < 4; ks2++) {
#pragma unroll
                    for (int g = 0; g < 2; g++) {
                        uint32_t vh[4][4], vl[4][4];
#pragma unroll
                        for (int q = 0; q < 4; q++) {
                            int np = g * 4 + q;
                            uint32_t voff = (uint32_t)((ks2 * 16 + a_la) * QSTR + np * 16 + a_k8) * 2;
                            ldsm4t(vh[q], sVh + voff);
                            ldsm4t(vl[q], sVl + voff);
                        }
#pragma unroll
                        for (int q = 0; q < 4; q++) {
                            int np = g * 4 + q;
                            mma16816(o[2 * np],     ph[ks2], vh[q]);
                            mma16816(o[2 * np + 1], ph[ks2], vh[q] + 2);
                        }
#pragma unroll
                        for (int q = 0; q < 4; q++) {
                            int np = g * 4 + q;
                            mma16816(o[2 * np],     ph[ks2], vl[q]);
                            mma16816(o[2 * np + 1], ph[ks2], vl[q] + 2);
                        }
                    }
                }
            }
            __syncthreads();
            if (t + 2 < ntiles) load_tile(t + 2, t & 1);
        }

        // epilogue: normalize, convert to fp16, write directly to O-proj input
#pragma unroll
        for (int rr = 0; rr < 2; rr++) {
            float inv = 1.0f / l[rr];
            int grow = qrow0 + r0 + rr * 8;
#pragma unroll
            for (int jj = 0; jj < 16; jj++) {
                int col = h * HD + jj * 8 + (lane & 3) * 2;
                __half2 hv = __floats2half2_rn(o[jj][rr * 2] * inv,
                                               o[jj][rr * 2 + 1] * inv);
                *(__half2*)&Oh[(size_t)grow * HID + col] = hv;
            }
        }
    }
}

extern "C" void kernel_launch(void* const* d_in, const int* in_sizes, int n_in,
                              void* d_out, int out_size)
{
    const float* hidden = (const float*)d_in[0];
    const int*   pos    = (const int*)d_in[1];
    const float* Wq     = (const float*)d_in[2];
    const float* Wk     = (const float*)d_in[3];
    const float* Wv     = (const float*)d_in[4];
    const float* Wo     = (const float*)d_in[5];
    float* out = (float*)d_out;

    float *qp, *kp, *vp;
    __half *ah, *wh, *wh2, *wh3;
    __half *qhp, *khp, *klp, *vhp, *vlp;
    cudaGetSymbolAddress((void**)&qp,  g_Q);
    cudaGetSymbolAddress((void**)&kp,  g_K);
    cudaGetSymbolAddress((void**)&vp,  g_V);
    cudaGetSymbolAddress((void**)&ah,  g_Ah);
    cudaGetSymbolAddress((void**)&wh,  g_Wh);
    cudaGetSymbolAddress((void**)&wh2, g_Wh2);
    cudaGetSymbolAddress((void**)&wh3, g_Wh3);
    cudaGetSymbolAddress((void**)&qhp, g_Qh);
    cudaGetSymbolAddress((void**)&khp, g_Kh);
    cudaGetSymbolAddress((void**)&klp, g_Kl);
    cudaGetSymbolAddress((void**)&vhp, g_Vh);
    cudaGetSymbolAddress((void**)&vlp, g_Vl);

    cudaFuncSetAttribute(gemm1_kernel,
                         cudaFuncAttributeMaxDynamicSharedMemorySize, G1SMEM);
    cudaFuncSetAttribute(flash_mma_kernel,
                         cudaFuncAttributeMaxDynamicSharedMemorySize, FSMEM_TOT);

    const int NA  = S_LEN * HID;
    const int NWQ = HID * HID;
    const int NWK = KVD * HID;

    // (1) act conv, (2) Wq conv, (3) Wk conv, (4) gemm1 Q <- ncu capture
    conv_f16_kernel<<<NA / 4 / 256, 256>>>(hidden, ah, NA);
    conv_f16_kernel<<<NWQ / 4 / 256, 256>>>(Wq, wh, NWQ);
    conv_f16_kernel<<<NWK / 4 / 256, 256>>>(Wk, wh2, NWK);
    gemm1_kernel<<<dim3(HID / 128, S_LEN / 128, 1), 256, G1SMEM>>>(
        ah, wh, qp, wh, qp, HID);

    // K + V projections, fused
    conv_f16_kernel<<<NWK / 4 / 256, 256>>>(Wv, wh3, NWK);
    gemm1_kernel<<<dim3(KVD / 128, S_LEN / 128, 2), 256, G1SMEM>>>(
        ah, wh2, kp, wh3, vp, KVD);

    rope_table_kernel<<<S_LEN * 64 / 256, 256>>>(pos);
    rope_split_kernel<<<S_LEN, 256>>>();
    split_f16_kernel<<<S_LEN * KVD / 4 / 256, 256>>>(vp, vhp, vlp, S_LEN * KVD);

    zero_ctr_kernel<<<1, 1>>>();
    flash_mma_kernel<<<148, 256, FSMEM_TOT>>>(
        qhp, khp, klp, vhp, vlp, ah);     // writes fp16 O-proj input directly

    // O projection (input g_Ah written by flash)
    conv_f16_kernel<<<NWQ / 4 / 256, 256>>>(Wo, wh, NWQ);
    gemm1_kernel<<<dim3(HID / 128, S_LEN / 128, 1), 256, G1SMEM>>>(
        ah, wh, out, wh, out, HID);
}